// round 3
// baseline (speedup 1.0000x reference)
#include <cuda_runtime.h>
#include <math.h>

#define BB   2
#define CC   256
#define NT   2304      // 48*48
#define NK   2324      // CLS + NT
#define CLSN 20
#define HDS  8
#define HD   32
#define MTOT (BB*NT)   // 4608
#define KTOT (BB*NK)   // 4648

__device__ float g_xq  [MTOT*CC];
__device__ float g_qin [MTOT*CC];
__device__ float g_kin [KTOT*CC];
__device__ float g_q   [MTOT*CC];
__device__ float g_kv  [KTOT*2*CC];
__device__ float g_ao  [MTOT*CC];
__device__ float g_x2  [MTOT*CC];
__device__ float g_ln3 [MTOT*CC];
__device__ float g_h   [MTOT*4*CC];
__device__ float g_y   [MTOT*CC];

// ---------------------------------------------------------------------------
// LN over x_query with NCHW -> (B, T, C) gather. Block = 32 t-rows.
// Writes XQ (pre-LN, residual) and QIN (post-LN).
// ---------------------------------------------------------------------------
__global__ __launch_bounds__(256) void ln_q_kernel(
    const float* __restrict__ X, const float* __restrict__ g1,
    const float* __restrict__ be1, float* __restrict__ XQ, float* __restrict__ QIN)
{
    __shared__ float s[32][257];
    const int b = blockIdx.y;
    const int t0 = blockIdx.x * 32;
    const int tw = threadIdx.x & 31;
    const int tc = threadIdx.x >> 5;   // 0..7
    for (int c0 = 0; c0 < 256; c0 += 8) {
        int c = c0 + tc;
        s[tw][c] = X[((size_t)(b * 256 + c)) * NT + t0 + tw];
    }
    __syncthreads();
    const int warp = threadIdx.x >> 5, lane = threadIdx.x & 31;
    for (int r = warp * 4; r < warp * 4 + 4; r++) {
        float v[8];
        float sum = 0.f, ss = 0.f;
#pragma unroll
        for (int u = 0; u < 8; u++) { float x = s[r][lane + 32 * u]; v[u] = x; sum += x; ss += x * x; }
#pragma unroll
        for (int o = 16; o; o >>= 1) {
            sum += __shfl_xor_sync(~0u, sum, o);
            ss  += __shfl_xor_sync(~0u, ss, o);
        }
        float mean = sum * (1.f / 256.f);
        float var  = ss * (1.f / 256.f) - mean * mean;
        float rs   = rsqrtf(var + 1e-5f);
        size_t base = ((size_t)(b * NT + t0 + r)) * 256;
#pragma unroll
        for (int u = 0; u < 8; u++) {
            int c = lane + 32 * u;
            XQ [base + c] = v[u];
            QIN[base + c] = (v[u] - mean) * rs * g1[c] + be1[c];
        }
    }
}

// ---------------------------------------------------------------------------
// LN over contiguous 256-wide rows. One warp per row.
// ---------------------------------------------------------------------------
__global__ __launch_bounds__(256) void ln_row_kernel(
    const float* __restrict__ X, const float* __restrict__ g,
    const float* __restrict__ be, float* __restrict__ Y, int rows)
{
    int w = (blockIdx.x * blockDim.x + threadIdx.x) >> 5;
    int lane = threadIdx.x & 31;
    if (w >= rows) return;
    const float* x = X + (size_t)w * 256;
    float4 v0 = *(const float4*)(x + lane * 4);
    float4 v1 = *(const float4*)(x + 128 + lane * 4);
    float sum = v0.x + v0.y + v0.z + v0.w + v1.x + v1.y + v1.z + v1.w;
    float ss  = v0.x*v0.x + v0.y*v0.y + v0.z*v0.z + v0.w*v0.w
              + v1.x*v1.x + v1.y*v1.y + v1.z*v1.z + v1.w*v1.w;
#pragma unroll
    for (int o = 16; o; o >>= 1) {
        sum += __shfl_xor_sync(~0u, sum, o);
        ss  += __shfl_xor_sync(~0u, ss, o);
    }
    float mean = sum * (1.f / 256.f);
    float var  = ss * (1.f / 256.f) - mean * mean;
    float rs   = rsqrtf(var + 1e-5f);
    float* y = Y + (size_t)w * 256;
    int c0 = lane * 4;
    float4 ga = *(const float4*)(g + c0),  ba = *(const float4*)(be + c0);
    float4 gb = *(const float4*)(g + 128 + c0), bb = *(const float4*)(be + 128 + c0);
    float4 o0, o1;
    o0.x = (v0.x - mean) * rs * ga.x + ba.x;
    o0.y = (v0.y - mean) * rs * ga.y + ba.y;
    o0.z = (v0.z - mean) * rs * ga.z + ba.z;
    o0.w = (v0.w - mean) * rs * ga.w + ba.w;
    o1.x = (v1.x - mean) * rs * gb.x + bb.x;
    o1.y = (v1.y - mean) * rs * gb.y + bb.y;
    o1.z = (v1.z - mean) * rs * gb.z + bb.z;
    o1.w = (v1.w - mean) * rs * gb.w + bb.w;
    *(float4*)(y + c0) = o0;
    *(float4*)(y + 128 + c0) = o1;
}

// ---------------------------------------------------------------------------
// Tiled fp32 GEMM: C[M,N] = A[M,K] @ W[K,N]  (+bias) (+gelu) (+residual)
// BM=128, BN=64, BK=16, 256 threads, 8x4 micro-tile per thread.
// ---------------------------------------------------------------------------
template<bool BIAS, bool RES, bool GELU>
__global__ __launch_bounds__(256) void gemm_k(
    const float* __restrict__ A, const float* __restrict__ W,
    const float* __restrict__ bias, const float* __restrict__ Res,
    float* __restrict__ C, int M, int N, int K)
{
    __shared__ float As[16][129];
    __shared__ float Bs[16][64];
    const int n0 = blockIdx.x * 64;
    const int m0 = blockIdx.y * 128;
    const int tid = threadIdx.x;
    const int tx = tid & 15, ty = tid >> 4;
    float acc[8][4];
#pragma unroll
    for (int i = 0; i < 8; i++)
#pragma unroll
        for (int j = 0; j < 4; j++) acc[i][j] = 0.f;

    const int arow = tid >> 2;    // 0..63
    const int ac4  = tid & 3;     // 0..3
    const int brow = tid >> 4;    // 0..15
    const int bc4  = tid & 15;    // 0..15

    for (int k0 = 0; k0 < K; k0 += 16) {
#pragma unroll
        for (int l = 0; l < 2; l++) {
            int r = arow + 64 * l;
            int m = m0 + r;
            float4 v = make_float4(0.f, 0.f, 0.f, 0.f);
            if (m < M) v = *(const float4*)(A + (size_t)m * K + k0 + ac4 * 4);
            As[ac4 * 4 + 0][r] = v.x;
            As[ac4 * 4 + 1][r] = v.y;
            As[ac4 * 4 + 2][r] = v.z;
            As[ac4 * 4 + 3][r] = v.w;
        }
        {
            float4 w4 = *(const float4*)(W + (size_t)(k0 + brow) * N + n0 + bc4 * 4);
            *(float4*)(&Bs[brow][bc4 * 4]) = w4;
        }
        __syncthreads();
#pragma unroll
        for (int kk = 0; kk < 16; kk++) {
            float4 bv = *(float4*)(&Bs[kk][tx * 4]);
            float a[8];
#pragma unroll
            for (int i = 0; i < 8; i++) a[i] = As[kk][ty * 8 + i];
#pragma unroll
            for (int i = 0; i < 8; i++) {
                acc[i][0] += a[i] * bv.x;
                acc[i][1] += a[i] * bv.y;
                acc[i][2] += a[i] * bv.z;
                acc[i][3] += a[i] * bv.w;
            }
        }
        __syncthreads();
    }
#pragma unroll
    for (int i = 0; i < 8; i++) {
        int m = m0 + ty * 8 + i;
        if (m >= M) continue;
        int n = n0 + tx * 4;
        float vals[4];
#pragma unroll
        for (int j = 0; j < 4; j++) {
            float v = acc[i][j];
            if (BIAS) v += bias[n + j];
            if (GELU) v = 0.5f * v * (1.f + erff(v * 0.70710678118654752f));
            if (RES)  v += Res[(size_t)m * N + n + j];
            vals[j] = v;
        }
        *(float4*)(C + (size_t)m * N + n) = make_float4(vals[0], vals[1], vals[2], vals[3]);
    }
}

// ---------------------------------------------------------------------------
// Fused attention. Block = 64 query rows for one (b, h). Two passes over keys:
//   pass A: per-segment exp-sums (no max needed; |s| << 1 at these scales)
//   pass B: p = exp(s)/Z_seg; w = (mask >= 0.3) * exp(p); out = (w @ V)/sum(w)
// Mask semantics: bern = (mask_u < 0.3) -> -1e12 -> excluded; exp underflow to
// exactly 0 makes this algebraic form exact.
// ---------------------------------------------------------------------------
#define ATT_SCALE 0.17677669529663687f

__global__ __launch_bounds__(256, 2) void attn_kernel(
    const float* __restrict__ Q, const float* __restrict__ KV,
    const float* __restrict__ MU, float* __restrict__ O)
{
    const int m0 = blockIdx.x * 64;
    const int h  = blockIdx.y;
    const int b  = blockIdx.z;
    const int tid = threadIdx.x;
    const int tm = tid >> 2;   // query row in tile 0..63
    const int tn = tid & 3;    // key lane 0..3

    __shared__ float Qs[64][36];
    __shared__ float Ks[64][36];
    __shared__ float Vs[64][36];
    __shared__ float Ms[64][68];
    __shared__ float sInv[2][64];

    {
        const float* qb = Q + ((size_t)(b * NT + m0)) * 256 + h * HD;
#pragma unroll
        for (int l = 0; l < 2; l++) {
            int f = tid + 256 * l; int r = f >> 3; int c4 = f & 7;
            float4 v = *(const float4*)(qb + (size_t)r * 256 + c4 * 4);
            *(float4*)(&Qs[r][c4 * 4]) = v;
        }
    }
    __syncthreads();
    float qr[32];
#pragma unroll
    for (int i = 0; i < 8; i++) {
        float4 v = *(float4*)(&Qs[tm][i * 4]);
        qr[4*i] = v.x; qr[4*i+1] = v.y; qr[4*i+2] = v.z; qr[4*i+3] = v.w;
    }

    const float* kb = KV + (size_t)b * NK * 512 + h * HD;
    const float* vb = kb + 256;

    // ---- pass A: segment exp-sums ----
    float z0 = 0.f, z1 = 0.f;
    for (int cb = 0; cb < NK; cb += 64) {
        int nv = min(64, NK - cb);
        __syncthreads();
#pragma unroll
        for (int l = 0; l < 2; l++) {
            int f = tid + 256 * l; int r = f >> 3; int c4 = f & 7;
            float4 v = make_float4(0.f, 0.f, 0.f, 0.f);
            if (r < nv) v = *(const float4*)(kb + (size_t)(cb + r) * 512 + c4 * 4);
            *(float4*)(&Ks[r][c4 * 4]) = v;
        }
        __syncthreads();
        for (int j = tn; j < nv; j += 4) {
            float s = 0.f;
#pragma unroll
            for (int i = 0; i < 8; i++) {
                float4 k4 = *(float4*)(&Ks[j][i * 4]);
                s += qr[4*i] * k4.x + qr[4*i+1] * k4.y + qr[4*i+2] * k4.z + qr[4*i+3] * k4.w;
            }
            float e = __expf(fminf(s * ATT_SCALE, 60.f));
            if (cb + j < CLSN) z0 += e; else z1 += e;
        }
    }
    z0 += __shfl_xor_sync(~0u, z0, 1); z0 += __shfl_xor_sync(~0u, z0, 2);
    z1 += __shfl_xor_sync(~0u, z1, 1); z1 += __shfl_xor_sync(~0u, z1, 2);
    __syncthreads();
    if (tn == 0) { sInv[0][tm] = 1.f / z0; sInv[1][tm] = 1.f / z1; }
    __syncthreads();
    const float iz0 = sInv[0][tm];
    const float iz1 = sInv[1][tm];

    // ---- pass B: masked second softmax + AV ----
    float acc[32];
#pragma unroll
    for (int i = 0; i < 32; i++) acc[i] = 0.f;
    float wsum = 0.f;
    const float* mb = MU + (((size_t)(b * HDS + h)) * NK + (CLSN + m0)) * NK;

    for (int cb = 0; cb < NK; cb += 64) {
        int nv = min(64, NK - cb);
        __syncthreads();
#pragma unroll
        for (int l = 0; l < 2; l++) {
            int f = tid + 256 * l; int r = f >> 3; int c4 = f & 7;
            float4 kvv = make_float4(0.f, 0.f, 0.f, 0.f);
            float4 vvv = make_float4(0.f, 0.f, 0.f, 0.f);
            if (r < nv) {
                kvv = *(const float4*)(kb + (size_t)(cb + r) * 512 + c4 * 4);
                vvv = *(const float4*)(vb + (size_t)(cb + r) * 512 + c4 * 4);
            }
            *(float4*)(&Ks[r][c4 * 4]) = kvv;
            *(float4*)(&Vs[r][c4 * 4]) = vvv;
        }
#pragma unroll
        for (int l = 0; l < 4; l++) {
            int f = tid + 256 * l; int r = f >> 4; int c4 = f & 15;
            if (c4 * 4 < nv) {
                float4 mv = *(const float4*)(mb + (size_t)r * NK + cb + c4 * 4);
                *(float4*)(&Ms[r][c4 * 4]) = mv;
            }
        }
        __syncthreads();
        for (int j = tn; j < nv; j += 4) {
            float s = 0.f;
#pragma unroll
            for (int i = 0; i < 8; i++) {
                float4 k4 = *(float4*)(&Ks[j][i * 4]);
                s += qr[4*i] * k4.x + qr[4*i+1] * k4.y + qr[4*i+2] * k4.z + qr[4*i+3] * k4.w;
            }
            float p = __expf(fminf(s * ATT_SCALE, 60.f)) * ((cb + j < CLSN) ? iz0 : iz1);
            // keep entries with mask_u >= 0.3 (bern=0); mask_u < 0.3 -> -1e12 -> 0
            float w = (Ms[tm][j] >= 0.3f) ? __expf(p) : 0.f;
            wsum += w;
#pragma unroll
            for (int i = 0; i < 8; i++) {
                float4 v4 = *(float4*)(&Vs[j][i * 4]);
                acc[4*i]   += w * v4.x;
                acc[4*i+1] += w * v4.y;
                acc[4*i+2] += w * v4.z;
                acc[4*i+3] += w * v4.w;
            }
        }
    }
#pragma unroll
    for (int i = 0; i < 32; i++) {
        acc[i] += __shfl_xor_sync(~0u, acc[i], 1);
        acc[i] += __shfl_xor_sync(~0u, acc[i], 2);
    }
    wsum += __shfl_xor_sync(~0u, wsum, 1);
    wsum += __shfl_xor_sync(~0u, wsum, 2);
    if (tn == 0) {
        float inv = 1.f / wsum;
        float* ob = O + ((size_t)(b * NT + m0 + tm)) * 256 + h * HD;
#pragma unroll
        for (int i = 0; i < 8; i++) {
            *(float4*)(ob + i * 4) = make_float4(acc[4*i] * inv, acc[4*i+1] * inv,
                                                 acc[4*i+2] * inv, acc[4*i+3] * inv);
        }
    }
}

// ---------------------------------------------------------------------------
// (B, T, C) -> (B, C, H, W) transpose
// ---------------------------------------------------------------------------
__global__ __launch_bounds__(256) void transpose_k(
    const float* __restrict__ Y, float* __restrict__ O)
{
    __shared__ float t[32][33];
    const int b = blockIdx.z;
    const int t0 = blockIdx.x * 32;
    const int c0 = blockIdx.y * 32;
    for (int i = threadIdx.y; i < 32; i += 8)
        t[i][threadIdx.x] = Y[((size_t)(b * NT + t0 + i)) * 256 + c0 + threadIdx.x];
    __syncthreads();
    for (int i = threadIdx.y; i < 32; i += 8)
        O[((size_t)(b * 256 + c0 + i)) * NT + t0 + threadIdx.x] = t[threadIdx.x][i];
}

// ---------------------------------------------------------------------------
extern "C" void kernel_launch(void* const* d_in, const int* in_sizes, int n_in,
                              void* d_out, int out_size)
{
    const float* x_query = (const float*)d_in[0];
    const float* x_key   = (const float*)d_in[1];
    const float* mask_u  = (const float*)d_in[2];
    const float* g1  = (const float*)d_in[3];
    const float* be1 = (const float*)d_in[4];
    const float* g2  = (const float*)d_in[5];
    const float* be2 = (const float*)d_in[6];
    const float* g3  = (const float*)d_in[7];
    const float* be3 = (const float*)d_in[8];
    const float* Wq  = (const float*)d_in[9];
    const float* Wkv = (const float*)d_in[10];
    // d_in[11] = Wcls: dead code (its outputs are sliced away by x[:, CLS:])
    const float* Wp  = (const float*)d_in[12];
    const float* bp  = (const float*)d_in[13];
    const float* W1  = (const float*)d_in[14];
    const float* bf1 = (const float*)d_in[15];
    const float* W2  = (const float*)d_in[16];
    const float* bf2 = (const float*)d_in[17];
    float* out = (float*)d_out;

    // __device__ globals must be resolved to device addresses on the host side.
    // cudaGetSymbolAddress is a pure lookup (no alloc, no stream op) -> capture-safe.
    static float *xq = nullptr, *qin, *kin, *q, *kv, *ao, *x2, *ln3, *hbuf, *y;
    if (!xq) {
        cudaGetSymbolAddress((void**)&xq,   g_xq);
        cudaGetSymbolAddress((void**)&qin,  g_qin);
        cudaGetSymbolAddress((void**)&kin,  g_kin);
        cudaGetSymbolAddress((void**)&q,    g_q);
        cudaGetSymbolAddress((void**)&kv,   g_kv);
        cudaGetSymbolAddress((void**)&ao,   g_ao);
        cudaGetSymbolAddress((void**)&x2,   g_x2);
        cudaGetSymbolAddress((void**)&ln3,  g_ln3);
        cudaGetSymbolAddress((void**)&hbuf, g_h);
        cudaGetSymbolAddress((void**)&y,    g_y);
    }

    // 1. LN(x_query) with NCHW gather; writes xq (residual) + qin
    ln_q_kernel<<<dim3(NT / 32, BB), 256>>>(x_query, g1, be1, xq, qin);
    // 2. LN(x_key) -> kin
    ln_row_kernel<<<(KTOT + 7) / 8, 256>>>(x_key, g2, be2, kin, KTOT);
    // 3. Q = qin @ Wq
    gemm_k<false, false, false><<<dim3(4, (MTOT + 127) / 128), 256>>>(
        qin, Wq, nullptr, nullptr, q, MTOT, 256, 256);
    // 4. KV = kin @ Wkv
    gemm_k<false, false, false><<<dim3(8, (KTOT + 127) / 128), 256>>>(
        kin, Wkv, nullptr, nullptr, kv, KTOT, 512, 256);
    // 5. attention -> ao
    attn_kernel<<<dim3(NT / 64, HDS, BB), 256>>>(q, kv, mask_u, ao);
    // 6. x2 = xq + (ao @ Wp + bp)
    gemm_k<true, true, false><<<dim3(4, (MTOT + 127) / 128), 256>>>(
        ao, Wp, bp, xq, x2, MTOT, 256, 256);
    // 7. ln3 = LN(x2)
    ln_row_kernel<<<(MTOT + 7) / 8, 256>>>(x2, g3, be3, ln3, MTOT);
    // 8. h = gelu(ln3 @ W1 + bf1)
    gemm_k<true, false, true><<<dim3(16, (MTOT + 127) / 128), 256>>>(
        ln3, W1, bf1, nullptr, hbuf, MTOT, 1024, 256);
    // 9. y = x2 + (h @ W2 + bf2)
    gemm_k<true, true, false><<<dim3(4, (MTOT + 127) / 128), 256>>>(
        hbuf, W2, bf2, x2, y, MTOT, 256, 1024);
    // 10. transpose to (B, C, H, W)
    transpose_k<<<dim3(NT / 32, 256 / 32, BB), dim3(32, 8)>>>(y, out);
}

// round 8
// speedup vs baseline: 1.6314x; 1.6314x over previous
#include <cuda_runtime.h>
#include <math.h>

#define BB   2
#define CC   256
#define NT   2304      // 48*48
#define NK   2324      // CLS + NT
#define CLSN 20
#define HDS  8
#define HD   32
#define MTOT (BB*NT)   // 4608
#define KTOT (BB*NK)   // 4648
#define ATT_SCALE 0.17677669529663687f

__device__ float g_xq  [MTOT*CC];
__device__ float g_qin [MTOT*CC];
__device__ float g_kin [KTOT*CC];
__device__ float g_q   [MTOT*CC];
__device__ float g_kv  [KTOT*2*CC];
__device__ float g_ao  [MTOT*CC];
__device__ float g_x2  [MTOT*CC];
__device__ float g_ln3 [MTOT*CC];
__device__ float g_h   [MTOT*4*CC];
__device__ float g_y   [MTOT*CC];

// ---------------------------------------------------------------------------
// tf32 tensor-core MMA (legacy HMMA path on sm_103a)
// D(16x8) += A(16x8) @ B(8x8);  A row-major frag, B col-major frag.
// ---------------------------------------------------------------------------
__device__ __forceinline__ void mma_tf32(float c[4], const unsigned a[4],
                                         unsigned b0, unsigned b1)
{
    asm volatile(
        "mma.sync.aligned.m16n8k8.row.col.f32.tf32.tf32.f32 "
        "{%0,%1,%2,%3}, {%4,%5,%6,%7}, {%8,%9}, {%0,%1,%2,%3};"
        : "+f"(c[0]), "+f"(c[1]), "+f"(c[2]), "+f"(c[3])
        : "r"(a[0]), "r"(a[1]), "r"(a[2]), "r"(a[3]), "r"(b0), "r"(b1));
}

// ---------------------------------------------------------------------------
// LN over x_query with NCHW -> (B, T, C) gather. Block = 32 t-rows.
// ---------------------------------------------------------------------------
__global__ __launch_bounds__(256) void ln_q_kernel(
    const float* __restrict__ X, const float* __restrict__ g1,
    const float* __restrict__ be1, float* __restrict__ XQ, float* __restrict__ QIN)
{
    __shared__ float s[32][257];
    const int b = blockIdx.y;
    const int t0 = blockIdx.x * 32;
    const int tw = threadIdx.x & 31;
    const int tc = threadIdx.x >> 5;   // 0..7
    for (int c0 = 0; c0 < 256; c0 += 8) {
        int c = c0 + tc;
        s[tw][c] = X[((size_t)(b * 256 + c)) * NT + t0 + tw];
    }
    __syncthreads();
    const int warp = threadIdx.x >> 5, lane = threadIdx.x & 31;
    for (int r = warp * 4; r < warp * 4 + 4; r++) {
        float v[8];
        float sum = 0.f, ss = 0.f;
#pragma unroll
        for (int u = 0; u < 8; u++) { float x = s[r][lane + 32 * u]; v[u] = x; sum += x; ss += x * x; }
#pragma unroll
        for (int o = 16; o; o >>= 1) {
            sum += __shfl_xor_sync(~0u, sum, o);
            ss  += __shfl_xor_sync(~0u, ss, o);
        }
        float mean = sum * (1.f / 256.f);
        float var  = ss * (1.f / 256.f) - mean * mean;
        float rs   = rsqrtf(var + 1e-5f);
        size_t base = ((size_t)(b * NT + t0 + r)) * 256;
#pragma unroll
        for (int u = 0; u < 8; u++) {
            int c = lane + 32 * u;
            XQ [base + c] = v[u];
            QIN[base + c] = (v[u] - mean) * rs * g1[c] + be1[c];
        }
    }
}

// ---------------------------------------------------------------------------
// LN over contiguous 256-wide rows. One warp per row.
// ---------------------------------------------------------------------------
__global__ __launch_bounds__(256) void ln_row_kernel(
    const float* __restrict__ X, const float* __restrict__ g,
    const float* __restrict__ be, float* __restrict__ Y, int rows)
{
    int w = (blockIdx.x * blockDim.x + threadIdx.x) >> 5;
    int lane = threadIdx.x & 31;
    if (w >= rows) return;
    const float* x = X + (size_t)w * 256;
    float4 v0 = *(const float4*)(x + lane * 4);
    float4 v1 = *(const float4*)(x + 128 + lane * 4);
    float sum = v0.x + v0.y + v0.z + v0.w + v1.x + v1.y + v1.z + v1.w;
    float ss  = v0.x*v0.x + v0.y*v0.y + v0.z*v0.z + v0.w*v0.w
              + v1.x*v1.x + v1.y*v1.y + v1.z*v1.z + v1.w*v1.w;
#pragma unroll
    for (int o = 16; o; o >>= 1) {
        sum += __shfl_xor_sync(~0u, sum, o);
        ss  += __shfl_xor_sync(~0u, ss, o);
    }
    float mean = sum * (1.f / 256.f);
    float var  = ss * (1.f / 256.f) - mean * mean;
    float rs   = rsqrtf(var + 1e-5f);
    float* y = Y + (size_t)w * 256;
    int c0 = lane * 4;
    float4 ga = *(const float4*)(g + c0),  ba = *(const float4*)(be + c0);
    float4 gb = *(const float4*)(g + 128 + c0), bb = *(const float4*)(be + 128 + c0);
    float4 o0, o1;
    o0.x = (v0.x - mean) * rs * ga.x + ba.x;
    o0.y = (v0.y - mean) * rs * ga.y + ba.y;
    o0.z = (v0.z - mean) * rs * ga.z + ba.z;
    o0.w = (v0.w - mean) * rs * ga.w + ba.w;
    o1.x = (v1.x - mean) * rs * gb.x + bb.x;
    o1.y = (v1.y - mean) * rs * gb.y + bb.y;
    o1.z = (v1.z - mean) * rs * gb.z + bb.z;
    o1.w = (v1.w - mean) * rs * gb.w + bb.w;
    *(float4*)(y + c0) = o0;
    *(float4*)(y + 128 + c0) = o1;
}

// ---------------------------------------------------------------------------
// Tiled fp32 GEMM: C[M,N] = A[M,K] @ W[K,N]  (+bias) (+gelu) (+residual)
// ---------------------------------------------------------------------------
template<bool BIAS, bool RES, bool GELU>
__global__ __launch_bounds__(256) void gemm_k(
    const float* __restrict__ A, const float* __restrict__ W,
    const float* __restrict__ bias, const float* __restrict__ Res,
    float* __restrict__ C, int M, int N, int K)
{
    __shared__ float As[16][129];
    __shared__ float Bs[16][64];
    const int n0 = blockIdx.x * 64;
    const int m0 = blockIdx.y * 128;
    const int tid = threadIdx.x;
    const int tx = tid & 15, ty = tid >> 4;
    float acc[8][4];
#pragma unroll
    for (int i = 0; i < 8; i++)
#pragma unroll
        for (int j = 0; j < 4; j++) acc[i][j] = 0.f;

    const int arow = tid >> 2;    // 0..63
    const int ac4  = tid & 3;     // 0..3
    const int brow = tid >> 4;    // 0..15
    const int bc4  = tid & 15;    // 0..15

    for (int k0 = 0; k0 < K; k0 += 16) {
#pragma unroll
        for (int l = 0; l < 2; l++) {
            int r = arow + 64 * l;
            int m = m0 + r;
            float4 v = make_float4(0.f, 0.f, 0.f, 0.f);
            if (m < M) v = *(const float4*)(A + (size_t)m * K + k0 + ac4 * 4);
            As[ac4 * 4 + 0][r] = v.x;
            As[ac4 * 4 + 1][r] = v.y;
            As[ac4 * 4 + 2][r] = v.z;
            As[ac4 * 4 + 3][r] = v.w;
        }
        {
            float4 w4 = *(const float4*)(W + (size_t)(k0 + brow) * N + n0 + bc4 * 4);
            *(float4*)(&Bs[brow][bc4 * 4]) = w4;
        }
        __syncthreads();
#pragma unroll
        for (int kk = 0; kk < 16; kk++) {
            float4 bv = *(float4*)(&Bs[kk][tx * 4]);
            float a[8];
#pragma unroll
            for (int i = 0; i < 8; i++) a[i] = As[kk][ty * 8 + i];
#pragma unroll
            for (int i = 0; i < 8; i++) {
                acc[i][0] += a[i] * bv.x;
                acc[i][1] += a[i] * bv.y;
                acc[i][2] += a[i] * bv.z;
                acc[i][3] += a[i] * bv.w;
            }
        }
        __syncthreads();
    }
#pragma unroll
    for (int i = 0; i < 8; i++) {
        int m = m0 + ty * 8 + i;
        if (m >= M) continue;
        int n = n0 + tx * 4;
        float vals[4];
#pragma unroll
        for (int j = 0; j < 4; j++) {
            float v = acc[i][j];
            if (BIAS) v += bias[n + j];
            if (GELU) v = 0.5f * v * (1.f + erff(v * 0.70710678118654752f));
            if (RES)  v += Res[(size_t)m * N + n + j];
            vals[j] = v;
        }
        *(float4*)(C + (size_t)m * N + n) = make_float4(vals[0], vals[1], vals[2], vals[3]);
    }
}

// ---------------------------------------------------------------------------
// Tensor-core attention (tf32 mma). Block = 128 query rows of one (b,h);
// 8 warps x 16 rows. Two passes over 37 key tiles of 64:
//   pass A: S = Q@K^T (mma) -> per-segment exp sums, all in registers.
//   pass B: recompute S, p = e*izSeg, w = (mask>=0.3)*exp(p); fragment-layout
//           shuffle C->A; out += w @ V (mma); divide by quad-reduced wsum.
// ---------------------------------------------------------------------------
__global__ __launch_bounds__(256, 2) void attn_mma_kernel(
    const float* __restrict__ Q, const float* __restrict__ KV,
    const float* __restrict__ MU, float* __restrict__ O)
{
    const int m0 = blockIdx.x * 128;
    const int h  = blockIdx.y;
    const int b  = blockIdx.z;
    const int tid  = threadIdx.x;
    const int w    = tid >> 5;
    const int lane = tid & 31;
    const int gr   = lane >> 2;   // groupID (row within 8)
    const int q4   = lane & 3;    // threadID in group

    __shared__ float Ks[64][36];   // stride 36: bank = (4*key+dim)%32 -> conflict-free
    __shared__ float Vs[64][36];

    // ---- Q fragments: rows m0+w*16+gr(+8), cols h*32 + kk*8 + q4(+4) ----
    unsigned qa[4][4];
    {
        const float* qb = Q + ((size_t)(b * NT + m0 + w * 16)) * 256 + h * HD;
#pragma unroll
        for (int kk = 0; kk < 4; kk++) {
            qa[kk][0] = __float_as_uint(qb[(size_t)gr * 256 + kk * 8 + q4]);
            qa[kk][1] = __float_as_uint(qb[(size_t)(gr + 8) * 256 + kk * 8 + q4]);
            qa[kk][2] = __float_as_uint(qb[(size_t)gr * 256 + kk * 8 + q4 + 4]);
            qa[kk][3] = __float_as_uint(qb[(size_t)(gr + 8) * 256 + kk * 8 + q4 + 4]);
        }
    }

    const float* kb = KV + (size_t)b * NK * 512 + h * HD;        // K part
    const float* vb = kb + 256;                                  // V part

    // ---- pass A: segment exp sums (rows lr0=w*16+gr, lr1=lr0+8) ----
    float zs0r0 = 0.f, zs1r0 = 0.f, zs0r1 = 0.f, zs1r1 = 0.f;

    for (int t = 0; t < 37; t++) {
        const int cb = t * 64;
        const int nv = min(64, NK - cb);
        __syncthreads();
#pragma unroll
        for (int l = 0; l < 2; l++) {
            int f = tid + 256 * l; int r = f >> 3; int c4 = f & 7;
            float4 v = make_float4(0.f, 0.f, 0.f, 0.f);
            if (r < nv) v = *(const float4*)(kb + (size_t)(cb + r) * 512 + c4 * 4);
            *(float4*)(&Ks[r][c4 * 4]) = v;
        }
        __syncthreads();
#pragma unroll
        for (int nn = 0; nn < 8; nn++) {
            float c[4] = {0.f, 0.f, 0.f, 0.f};
#pragma unroll
            for (int kk = 0; kk < 4; kk++) {
                unsigned b0 = __float_as_uint(Ks[nn * 8 + gr][kk * 8 + q4]);
                unsigned b1 = __float_as_uint(Ks[nn * 8 + gr][kk * 8 + q4 + 4]);
                mma_tf32(c, qa[kk], b0, b1);
            }
            const int g0 = cb + nn * 8 + 2 * q4;
            const int g1 = g0 + 1;
            if (g0 < NK) {
                float e0 = __expf(c[0] * ATT_SCALE);
                float e2 = __expf(c[2] * ATT_SCALE);
                if (g0 < CLSN) { zs0r0 += e0; zs0r1 += e2; }
                else           { zs1r0 += e0; zs1r1 += e2; }
            }
            if (g1 < NK) {
                float e1 = __expf(c[1] * ATT_SCALE);
                float e3 = __expf(c[3] * ATT_SCALE);
                if (g1 < CLSN) { zs0r0 += e1; zs0r1 += e3; }
                else           { zs1r0 += e1; zs1r1 += e3; }
            }
        }
    }
    // quad all-reduce (lanes differing in bits 0-1 cover all 64 cols per row)
#pragma unroll
    for (int o = 1; o <= 2; o <<= 1) {
        zs0r0 += __shfl_xor_sync(~0u, zs0r0, o);
        zs1r0 += __shfl_xor_sync(~0u, zs1r0, o);
        zs0r1 += __shfl_xor_sync(~0u, zs0r1, o);
        zs1r1 += __shfl_xor_sync(~0u, zs1r1, o);
    }
    const float iza0 = 1.f / zs0r0;   // row lr0, seg0
    const float izb0 = 1.f / zs1r0;   // row lr0, seg1
    const float iza1 = 1.f / zs0r1;   // row lr1, seg0
    const float izb1 = 1.f / zs1r1;   // row lr1, seg1

    // ---- pass B ----
    float av[4][4];
#pragma unroll
    for (int i = 0; i < 4; i++)
#pragma unroll
        for (int j = 0; j < 4; j++) av[i][j] = 0.f;
    float ws0 = 0.f, ws1 = 0.f;

    const float* mrow0 = MU + (((size_t)(b * HDS + h)) * NK + CLSN + m0 + w * 16 + gr) * NK;
    const float* mrow1 = mrow0 + (size_t)8 * NK;
    const int base = lane & ~3;
    const int s0 = base + (q4 >> 1);       // source lane for col q4
    const int s1 = s0 + 2;                 // source lane for col q4+4

    for (int t = 0; t < 37; t++) {
        const int cb = t * 64;
        const int nv = min(64, NK - cb);
        __syncthreads();
#pragma unroll
        for (int l = 0; l < 2; l++) {
            int f = tid + 256 * l; int r = f >> 3; int c4 = f & 7;
            float4 kvv = make_float4(0.f, 0.f, 0.f, 0.f);
            float4 vvv = make_float4(0.f, 0.f, 0.f, 0.f);
            if (r < nv) {
                kvv = *(const float4*)(kb + (size_t)(cb + r) * 512 + c4 * 4);
                vvv = *(const float4*)(vb + (size_t)(cb + r) * 512 + c4 * 4);
            }
            *(float4*)(&Ks[r][c4 * 4]) = kvv;
            *(float4*)(&Vs[r][c4 * 4]) = vvv;
        }
        __syncthreads();
#pragma unroll
        for (int nn = 0; nn < 8; nn++) {
            float c[4] = {0.f, 0.f, 0.f, 0.f};
#pragma unroll
            for (int kk = 0; kk < 4; kk++) {
                unsigned b0 = __float_as_uint(Ks[nn * 8 + gr][kk * 8 + q4]);
                unsigned b1 = __float_as_uint(Ks[nn * 8 + gr][kk * 8 + q4 + 4]);
                mma_tf32(c, qa[kk], b0, b1);
            }
            const int g0 = cb + nn * 8 + 2 * q4;
            const int g1 = g0 + 1;
            // mask loads (8B aligned float2, 100% sector use)
            float m00 = 0.f, m01 = 0.f, m10 = 0.f, m11 = 0.f;
            if (g1 < NK) {
                float2 ma = *(const float2*)(mrow0 + g0); m00 = ma.x; m01 = ma.y;
                float2 mb2 = *(const float2*)(mrow1 + g0); m10 = mb2.x; m11 = mb2.y;
            } else if (g0 < NK) {
                m00 = mrow0[g0]; m10 = mrow1[g0];
            }
            float w0 = 0.f, w1 = 0.f, w2 = 0.f, w3 = 0.f;
            if (g0 < NK) {
                bool cls = g0 < CLSN;
                if (m00 >= 0.3f) w0 = __expf(__expf(c[0] * ATT_SCALE) * (cls ? iza0 : izb0));
                if (m10 >= 0.3f) w2 = __expf(__expf(c[2] * ATT_SCALE) * (cls ? iza1 : izb1));
            }
            if (g1 < NK) {
                bool cls = g1 < CLSN;
                if (m01 >= 0.3f) w1 = __expf(__expf(c[1] * ATT_SCALE) * (cls ? iza0 : izb0));
                if (m11 >= 0.3f) w3 = __expf(__expf(c[3] * ATT_SCALE) * (cls ? iza1 : izb1));
            }
            ws0 += w0 + w1;
            ws1 += w2 + w3;
            // ---- fragment layout conversion C -> A (within quad) ----
            float u0 = __shfl_sync(~0u, w0, s0);
            float u1 = __shfl_sync(~0u, w1, s0);
            float u2 = __shfl_sync(~0u, w2, s0);
            float u3 = __shfl_sync(~0u, w3, s0);
            float v0 = __shfl_sync(~0u, w0, s1);
            float v1 = __shfl_sync(~0u, w1, s1);
            float v2 = __shfl_sync(~0u, w2, s1);
            float v3 = __shfl_sync(~0u, w3, s1);
            unsigned wa[4];
            wa[0] = __float_as_uint((q4 & 1) ? u1 : u0);   // row gr,   col q4
            wa[1] = __float_as_uint((q4 & 1) ? u3 : u2);   // row gr+8, col q4
            wa[2] = __float_as_uint((q4 & 1) ? v1 : v0);   // row gr,   col q4+4
            wa[3] = __float_as_uint((q4 & 1) ? v3 : v2);   // row gr+8, col q4+4
            // ---- AV: out += w @ V  (contraction over this 8-key chunk) ----
#pragma unroll
            for (int nn2 = 0; nn2 < 4; nn2++) {
                unsigned b0 = __float_as_uint(Vs[nn * 8 + q4][nn2 * 8 + gr]);
                unsigned b1 = __float_as_uint(Vs[nn * 8 + q4 + 4][nn2 * 8 + gr]);
                mma_tf32(av[nn2], wa, b0, b1);
            }
        }
    }
    // wsum quad all-reduce
#pragma unroll
    for (int o = 1; o <= 2; o <<= 1) {
        ws0 += __shfl_xor_sync(~0u, ws0, o);
        ws1 += __shfl_xor_sync(~0u, ws1, o);
    }
    const float inv0 = 1.f / ws0;
    const float inv1 = 1.f / ws1;

    float* ob0 = O + ((size_t)(b * NT + m0 + w * 16 + gr)) * 256 + h * HD;
    float* ob1 = ob0 + (size_t)8 * 256;
#pragma unroll
    for (int nn2 = 0; nn2 < 4; nn2++) {
        *(float2*)(ob0 + nn2 * 8 + 2 * q4) = make_float2(av[nn2][0] * inv0, av[nn2][1] * inv0);
        *(float2*)(ob1 + nn2 * 8 + 2 * q4) = make_float2(av[nn2][2] * inv1, av[nn2][3] * inv1);
    }
}

// ---------------------------------------------------------------------------
// (B, T, C) -> (B, C, H, W) transpose
// ---------------------------------------------------------------------------
__global__ __launch_bounds__(256) void transpose_k(
    const float* __restrict__ Y, float* __restrict__ O)
{
    __shared__ float t[32][33];
    const int b = blockIdx.z;
    const int t0 = blockIdx.x * 32;
    const int c0 = blockIdx.y * 32;
    for (int i = threadIdx.y; i < 32; i += 8)
        t[i][threadIdx.x] = Y[((size_t)(b * NT + t0 + i)) * 256 + c0 + threadIdx.x];
    __syncthreads();
    for (int i = threadIdx.y; i < 32; i += 8)
        O[((size_t)(b * 256 + c0 + i)) * NT + t0 + threadIdx.x] = t[threadIdx.x][i];
}

// ---------------------------------------------------------------------------
extern "C" void kernel_launch(void* const* d_in, const int* in_sizes, int n_in,
                              void* d_out, int out_size)
{
    const float* x_query = (const float*)d_in[0];
    const float* x_key   = (const float*)d_in[1];
    const float* mask_u  = (const float*)d_in[2];
    const float* g1  = (const float*)d_in[3];
    const float* be1 = (const float*)d_in[4];
    const float* g2  = (const float*)d_in[5];
    const float* be2 = (const float*)d_in[6];
    const float* g3  = (const float*)d_in[7];
    const float* be3 = (const float*)d_in[8];
    const float* Wq  = (const float*)d_in[9];
    const float* Wkv = (const float*)d_in[10];
    // d_in[11] = Wcls: dead code (outputs sliced away by x[:, CLS:])
    const float* Wp  = (const float*)d_in[12];
    const float* bp  = (const float*)d_in[13];
    const float* W1  = (const float*)d_in[14];
    const float* bf1 = (const float*)d_in[15];
    const float* W2  = (const float*)d_in[16];
    const float* bf2 = (const float*)d_in[17];
    float* out = (float*)d_out;

    static float *xq = nullptr, *qin, *kin, *q, *kv, *ao, *x2, *ln3, *hbuf, *y;
    if (!xq) {
        cudaGetSymbolAddress((void**)&xq,   g_xq);
        cudaGetSymbolAddress((void**)&qin,  g_qin);
        cudaGetSymbolAddress((void**)&kin,  g_kin);
        cudaGetSymbolAddress((void**)&q,    g_q);
        cudaGetSymbolAddress((void**)&kv,   g_kv);
        cudaGetSymbolAddress((void**)&ao,   g_ao);
        cudaGetSymbolAddress((void**)&x2,   g_x2);
        cudaGetSymbolAddress((void**)&ln3,  g_ln3);
        cudaGetSymbolAddress((void**)&hbuf, g_h);
        cudaGetSymbolAddress((void**)&y,    g_y);
    }

    // 1. LN(x_query) with NCHW gather; writes xq (residual) + qin
    ln_q_kernel<<<dim3(NT / 32, BB), 256>>>(x_query, g1, be1, xq, qin);
    // 2. LN(x_key) -> kin
    ln_row_kernel<<<(KTOT + 7) / 8, 256>>>(x_key, g2, be2, kin, KTOT);
    // 3. Q = qin @ Wq
    gemm_k<false, false, false><<<dim3(4, (MTOT + 127) / 128), 256>>>(
        qin, Wq, nullptr, nullptr, q, MTOT, 256, 256);
    // 4. KV = kin @ Wkv
    gemm_k<false, false, false><<<dim3(8, (KTOT + 127) / 128), 256>>>(
        kin, Wkv, nullptr, nullptr, kv, KTOT, 512, 256);
    // 5. attention (tensor-core tf32) -> ao
    attn_mma_kernel<<<dim3(NT / 128, HDS, BB), 256>>>(q, kv, mask_u, ao);
    // 6. x2 = xq + (ao @ Wp + bp)
    gemm_k<true, true, false><<<dim3(4, (MTOT + 127) / 128), 256>>>(
        ao, Wp, bp, xq, x2, MTOT, 256, 256);
    // 7. ln3 = LN(x2)
    ln_row_kernel<<<(MTOT + 7) / 8, 256>>>(x2, g3, be3, ln3, MTOT);
    // 8. h = gelu(ln3 @ W1 + bf1)
    gemm_k<true, false, true><<<dim3(16, (MTOT + 127) / 128), 256>>>(
        ln3, W1, bf1, nullptr, hbuf, MTOT, 1024, 256);
    // 9. y = x2 + (h @ W2 + bf2)
    gemm_k<true, true, false><<<dim3(4, (MTOT + 127) / 128), 256>>>(
        hbuf, W2, bf2, x2, y, MTOT, 256, 1024);
    // 10. transpose to (B, C, H, W)
    transpose_k<<<dim3(NT / 32, 256 / 32, BB), dim3(32, 8)>>>(y, out);
}

// round 9
// speedup vs baseline: 1.9655x; 1.2048x over previous
#include <cuda_runtime.h>
#include <math.h>

#define BB   2
#define CC   256
#define NT   2304      // 48*48
#define NK   2324      // CLS + NT
#define CLSN 20
#define HDS  8
#define HD   32
#define MTOT (BB*NT)   // 4608
#define KTOT (BB*NK)   // 4648
#define ATT_SCALE 0.17677669529663687f

__device__ float g_xq  [MTOT*CC];
__device__ float g_qin [MTOT*CC];
__device__ float g_kin [KTOT*CC];
__device__ float g_q   [MTOT*CC];
__device__ float g_kv  [KTOT*2*CC];
__device__ float g_ao  [MTOT*CC];
__device__ float g_x2  [MTOT*CC];
__device__ float g_ln3 [MTOT*CC];
__device__ float g_h   [MTOT*4*CC];
__device__ float g_y   [MTOT*CC];

// ---------------------------------------------------------------------------
// tf32 tensor-core MMA: D(16x8) += A(16x8) @ B(8x8)
// ---------------------------------------------------------------------------
__device__ __forceinline__ void mma_tf32(float c[4], const unsigned a[4],
                                         unsigned b0, unsigned b1)
{
    asm volatile(
        "mma.sync.aligned.m16n8k8.row.col.f32.tf32.tf32.f32 "
        "{%0,%1,%2,%3}, {%4,%5,%6,%7}, {%8,%9}, {%0,%1,%2,%3};"
        : "+f"(c[0]), "+f"(c[1]), "+f"(c[2]), "+f"(c[3])
        : "r"(a[0]), "r"(a[1]), "r"(a[2]), "r"(a[3]), "r"(b0), "r"(b1));
}

// exp(p) for p in [0, ~1.1] — degree-6 Taylor about 0.5, rel err < 3e-6.
// Runs entirely on the FMA pipe (no MUFU).
__device__ __forceinline__ float exp01(float p)
{
    float r = p - 0.5f;
    float q = 1.f + r * (1.f + r * (0.5f + r * (0.16666667f +
              r * (0.041666667f + r * (0.0083333333f + r * 0.0013888889f)))));
    return 1.6487212707001282f * q;
}

// ---------------------------------------------------------------------------
// LN over x_query with NCHW -> (B, T, C) gather. Block = 32 t-rows.
// ---------------------------------------------------------------------------
__global__ __launch_bounds__(256) void ln_q_kernel(
    const float* __restrict__ X, const float* __restrict__ g1,
    const float* __restrict__ be1, float* __restrict__ XQ, float* __restrict__ QIN)
{
    __shared__ float s[32][257];
    const int b = blockIdx.y;
    const int t0 = blockIdx.x * 32;
    const int tw = threadIdx.x & 31;
    const int tc = threadIdx.x >> 5;   // 0..7
    for (int c0 = 0; c0 < 256; c0 += 8) {
        int c = c0 + tc;
        s[tw][c] = X[((size_t)(b * 256 + c)) * NT + t0 + tw];
    }
    __syncthreads();
    const int warp = threadIdx.x >> 5, lane = threadIdx.x & 31;
    for (int r = warp * 4; r < warp * 4 + 4; r++) {
        float v[8];
        float sum = 0.f, ss = 0.f;
#pragma unroll
        for (int u = 0; u < 8; u++) { float x = s[r][lane + 32 * u]; v[u] = x; sum += x; ss += x * x; }
#pragma unroll
        for (int o = 16; o; o >>= 1) {
            sum += __shfl_xor_sync(~0u, sum, o);
            ss  += __shfl_xor_sync(~0u, ss, o);
        }
        float mean = sum * (1.f / 256.f);
        float var  = ss * (1.f / 256.f) - mean * mean;
        float rs   = rsqrtf(var + 1e-5f);
        size_t base = ((size_t)(b * NT + t0 + r)) * 256;
#pragma unroll
        for (int u = 0; u < 8; u++) {
            int c = lane + 32 * u;
            XQ [base + c] = v[u];
            QIN[base + c] = (v[u] - mean) * rs * g1[c] + be1[c];
        }
    }
}

// ---------------------------------------------------------------------------
// LN over contiguous 256-wide rows. One warp per row.
// ---------------------------------------------------------------------------
__global__ __launch_bounds__(256) void ln_row_kernel(
    const float* __restrict__ X, const float* __restrict__ g,
    const float* __restrict__ be, float* __restrict__ Y, int rows)
{
    int w = (blockIdx.x * blockDim.x + threadIdx.x) >> 5;
    int lane = threadIdx.x & 31;
    if (w >= rows) return;
    const float* x = X + (size_t)w * 256;
    float4 v0 = *(const float4*)(x + lane * 4);
    float4 v1 = *(const float4*)(x + 128 + lane * 4);
    float sum = v0.x + v0.y + v0.z + v0.w + v1.x + v1.y + v1.z + v1.w;
    float ss  = v0.x*v0.x + v0.y*v0.y + v0.z*v0.z + v0.w*v0.w
              + v1.x*v1.x + v1.y*v1.y + v1.z*v1.z + v1.w*v1.w;
#pragma unroll
    for (int o = 16; o; o >>= 1) {
        sum += __shfl_xor_sync(~0u, sum, o);
        ss  += __shfl_xor_sync(~0u, ss, o);
    }
    float mean = sum * (1.f / 256.f);
    float var  = ss * (1.f / 256.f) - mean * mean;
    float rs   = rsqrtf(var + 1e-5f);
    float* y = Y + (size_t)w * 256;
    int c0 = lane * 4;
    float4 ga = *(const float4*)(g + c0),  ba = *(const float4*)(be + c0);
    float4 gb = *(const float4*)(g + 128 + c0), bb = *(const float4*)(be + 128 + c0);
    float4 o0, o1;
    o0.x = (v0.x - mean) * rs * ga.x + ba.x;
    o0.y = (v0.y - mean) * rs * ga.y + ba.y;
    o0.z = (v0.z - mean) * rs * ga.z + ba.z;
    o0.w = (v0.w - mean) * rs * ga.w + ba.w;
    o1.x = (v1.x - mean) * rs * gb.x + bb.x;
    o1.y = (v1.y - mean) * rs * gb.y + bb.y;
    o1.z = (v1.z - mean) * rs * gb.z + bb.z;
    o1.w = (v1.w - mean) * rs * gb.w + bb.w;
    *(float4*)(y + c0) = o0;
    *(float4*)(y + 128 + c0) = o1;
}

// ---------------------------------------------------------------------------
// tf32 tensor-core GEMM: C[M,N] = A[M,K] @ W[K,N] (+bias)(+gelu)(+residual)
// BM=128, BN=64, BK=16. 8 warps; warp tile 32x32 (2x4 m16n8 frags).
// Smem padding chosen for conflict-free fragment LDS:
//   As[m][36]: bank=(4m+k)%32 permutes lanes; Bs[k][72]: bank=(8k+n)%32.
// ---------------------------------------------------------------------------
template<bool BIAS, bool RES, bool GELU>
__global__ __launch_bounds__(256, 2) void gemm_mma(
    const float* __restrict__ A, const float* __restrict__ W,
    const float* __restrict__ bias, const float* __restrict__ Res,
    float* __restrict__ C, int M, int N, int K)
{
    __shared__ float As[128][36];
    __shared__ float Bs[16][72];
    const int n0 = blockIdx.x * 64;
    const int m0 = blockIdx.y * 128;
    const int tid  = threadIdx.x;
    const int w    = tid >> 5;
    const int lane = tid & 31;
    const int wm = (w & 3) * 32;      // warp m-offset in tile
    const int wn = (w >> 2) * 32;     // warp n-offset in tile
    const int gr = lane >> 2, q4 = lane & 3;

    float acc[2][4][4];
#pragma unroll
    for (int mi = 0; mi < 2; mi++)
#pragma unroll
        for (int ni = 0; ni < 4; ni++)
#pragma unroll
            for (int j = 0; j < 4; j++) acc[mi][ni][j] = 0.f;

    const int ar = tid >> 2;          // 0..63
    const int ac4 = tid & 3;          // 0..3
    const int bk = tid >> 4;          // 0..15
    const int bc4 = tid & 15;         // 0..15

    for (int k0 = 0; k0 < K; k0 += 16) {
#pragma unroll
        for (int l = 0; l < 2; l++) {
            int row = ar + l * 64;
            float4 v = make_float4(0.f, 0.f, 0.f, 0.f);
            if (m0 + row < M) v = *(const float4*)(A + (size_t)(m0 + row) * K + k0 + ac4 * 4);
            As[row][ac4 * 4 + 0] = v.x;
            As[row][ac4 * 4 + 1] = v.y;
            As[row][ac4 * 4 + 2] = v.z;
            As[row][ac4 * 4 + 3] = v.w;
        }
        {
            float4 v = *(const float4*)(W + (size_t)(k0 + bk) * N + n0 + bc4 * 4);
            Bs[bk][bc4 * 4 + 0] = v.x;
            Bs[bk][bc4 * 4 + 1] = v.y;
            Bs[bk][bc4 * 4 + 2] = v.z;
            Bs[bk][bc4 * 4 + 3] = v.w;
        }
        __syncthreads();
#pragma unroll
        for (int kk = 0; kk < 2; kk++) {
            unsigned a[2][4];
#pragma unroll
            for (int mi = 0; mi < 2; mi++) {
                int rb = wm + mi * 16;
                a[mi][0] = __float_as_uint(As[rb + gr    ][kk * 8 + q4]);
                a[mi][1] = __float_as_uint(As[rb + gr + 8][kk * 8 + q4]);
                a[mi][2] = __float_as_uint(As[rb + gr    ][kk * 8 + q4 + 4]);
                a[mi][3] = __float_as_uint(As[rb + gr + 8][kk * 8 + q4 + 4]);
            }
#pragma unroll
            for (int ni = 0; ni < 4; ni++) {
                unsigned b0 = __float_as_uint(Bs[kk * 8 + q4    ][wn + ni * 8 + gr]);
                unsigned b1 = __float_as_uint(Bs[kk * 8 + q4 + 4][wn + ni * 8 + gr]);
#pragma unroll
                for (int mi = 0; mi < 2; mi++)
                    mma_tf32(acc[mi][ni], a[mi], b0, b1);
            }
        }
        __syncthreads();
    }
    // epilogue: rows m0+wm+mi*16+gr(+8), cols n0+wn+ni*8+2q4(+1)
#pragma unroll
    for (int mi = 0; mi < 2; mi++) {
        int row0 = m0 + wm + mi * 16 + gr;
        int row1 = row0 + 8;
#pragma unroll
        for (int ni = 0; ni < 4; ni++) {
            int cn = n0 + wn + ni * 8 + 2 * q4;
            float b0v = 0.f, b1v = 0.f;
            if (BIAS) { b0v = bias[cn]; b1v = bias[cn + 1]; }
#pragma unroll
            for (int half = 0; half < 2; half++) {
                int r = half ? row1 : row0;
                if (r >= M) continue;
                float v0 = acc[mi][ni][half * 2 + 0] + b0v;
                float v1 = acc[mi][ni][half * 2 + 1] + b1v;
                if (GELU) {
                    v0 = 0.5f * v0 * (1.f + erff(v0 * 0.70710678118654752f));
                    v1 = 0.5f * v1 * (1.f + erff(v1 * 0.70710678118654752f));
                }
                if (RES) {
                    v0 += Res[(size_t)r * N + cn];
                    v1 += Res[(size_t)r * N + cn + 1];
                }
                *(float2*)(C + (size_t)r * N + cn) = make_float2(v0, v1);
            }
        }
    }
}

// ---------------------------------------------------------------------------
// Tensor-core attention (tf32 mma). Block = 128 query rows of one (b,h);
// 8 warps x 16 rows. Two passes over 37 key tiles of 64.
// ---------------------------------------------------------------------------
__global__ __launch_bounds__(256, 2) void attn_mma_kernel(
    const float* __restrict__ Q, const float* __restrict__ KV,
    const float* __restrict__ MU, float* __restrict__ O)
{
    const int m0 = blockIdx.x * 128;
    const int h  = blockIdx.y;
    const int b  = blockIdx.z;
    const int tid  = threadIdx.x;
    const int w    = tid >> 5;
    const int lane = tid & 31;
    const int gr   = lane >> 2;   // groupID (row within 8)
    const int q4   = lane & 3;    // threadID in group

    __shared__ float Ks[64][36];   // stride 36: bank = (4*key+dim)%32 -> conflict-free
    __shared__ float Vs[64][36];

    unsigned qa[4][4];
    {
        const float* qb = Q + ((size_t)(b * NT + m0 + w * 16)) * 256 + h * HD;
#pragma unroll
        for (int kk = 0; kk < 4; kk++) {
            qa[kk][0] = __float_as_uint(qb[(size_t)gr * 256 + kk * 8 + q4]);
            qa[kk][1] = __float_as_uint(qb[(size_t)(gr + 8) * 256 + kk * 8 + q4]);
            qa[kk][2] = __float_as_uint(qb[(size_t)gr * 256 + kk * 8 + q4 + 4]);
            qa[kk][3] = __float_as_uint(qb[(size_t)(gr + 8) * 256 + kk * 8 + q4 + 4]);
        }
    }

    const float* kb = KV + (size_t)b * NK * 512 + h * HD;        // K part
    const float* vb = kb + 256;                                  // V part

    // ---- pass A: segment exp sums ----
    float zs0r0 = 0.f, zs1r0 = 0.f, zs0r1 = 0.f, zs1r1 = 0.f;

    for (int t = 0; t < 37; t++) {
        const int cb = t * 64;
        const int nv = min(64, NK - cb);
        __syncthreads();
#pragma unroll
        for (int l = 0; l < 2; l++) {
            int f = tid + 256 * l; int r = f >> 3; int c4 = f & 7;
            float4 v = make_float4(0.f, 0.f, 0.f, 0.f);
            if (r < nv) v = *(const float4*)(kb + (size_t)(cb + r) * 512 + c4 * 4);
            *(float4*)(&Ks[r][c4 * 4]) = v;
        }
        __syncthreads();
#pragma unroll
        for (int nn = 0; nn < 8; nn++) {
            float c[4] = {0.f, 0.f, 0.f, 0.f};
#pragma unroll
            for (int kk = 0; kk < 4; kk++) {
                unsigned b0 = __float_as_uint(Ks[nn * 8 + gr][kk * 8 + q4]);
                unsigned b1 = __float_as_uint(Ks[nn * 8 + gr][kk * 8 + q4 + 4]);
                mma_tf32(c, qa[kk], b0, b1);
            }
            const int g0 = cb + nn * 8 + 2 * q4;
            const int g1 = g0 + 1;
            if (g0 < NK) {
                float e0 = __expf(c[0] * ATT_SCALE);
                float e2 = __expf(c[2] * ATT_SCALE);
                if (g0 < CLSN) { zs0r0 += e0; zs0r1 += e2; }
                else           { zs1r0 += e0; zs1r1 += e2; }
            }
            if (g1 < NK) {
                float e1 = __expf(c[1] * ATT_SCALE);
                float e3 = __expf(c[3] * ATT_SCALE);
                if (g1 < CLSN) { zs0r0 += e1; zs0r1 += e3; }
                else           { zs1r0 += e1; zs1r1 += e3; }
            }
        }
    }
#pragma unroll
    for (int o = 1; o <= 2; o <<= 1) {
        zs0r0 += __shfl_xor_sync(~0u, zs0r0, o);
        zs1r0 += __shfl_xor_sync(~0u, zs1r0, o);
        zs0r1 += __shfl_xor_sync(~0u, zs0r1, o);
        zs1r1 += __shfl_xor_sync(~0u, zs1r1, o);
    }
    const float iza0 = 1.f / zs0r0;
    const float izb0 = 1.f / zs1r0;
    const float iza1 = 1.f / zs0r1;
    const float izb1 = 1.f / zs1r1;

    // ---- pass B ----
    float av[4][4];
#pragma unroll
    for (int i = 0; i < 4; i++)
#pragma unroll
        for (int j = 0; j < 4; j++) av[i][j] = 0.f;
    float ws0 = 0.f, ws1 = 0.f;

    const float* mrow0 = MU + (((size_t)(b * HDS + h)) * NK + CLSN + m0 + w * 16 + gr) * NK;
    const float* mrow1 = mrow0 + (size_t)8 * NK;
    const int base = lane & ~3;
    const int s0 = base + (q4 >> 1);
    const int s1 = s0 + 2;

    for (int t = 0; t < 37; t++) {
        const int cb = t * 64;
        const int nv = min(64, NK - cb);
        __syncthreads();
#pragma unroll
        for (int l = 0; l < 2; l++) {
            int f = tid + 256 * l; int r = f >> 3; int c4 = f & 7;
            float4 kvv = make_float4(0.f, 0.f, 0.f, 0.f);
            float4 vvv = make_float4(0.f, 0.f, 0.f, 0.f);
            if (r < nv) {
                kvv = *(const float4*)(kb + (size_t)(cb + r) * 512 + c4 * 4);
                vvv = *(const float4*)(vb + (size_t)(cb + r) * 512 + c4 * 4);
            }
            *(float4*)(&Ks[r][c4 * 4]) = kvv;
            *(float4*)(&Vs[r][c4 * 4]) = vvv;
        }
        __syncthreads();
#pragma unroll
        for (int nn = 0; nn < 8; nn++) {
            float c[4] = {0.f, 0.f, 0.f, 0.f};
#pragma unroll
            for (int kk = 0; kk < 4; kk++) {
                unsigned b0 = __float_as_uint(Ks[nn * 8 + gr][kk * 8 + q4]);
                unsigned b1 = __float_as_uint(Ks[nn * 8 + gr][kk * 8 + q4 + 4]);
                mma_tf32(c, qa[kk], b0, b1);
            }
            const int g0 = cb + nn * 8 + 2 * q4;
            const int g1 = g0 + 1;
            float m00 = 0.f, m01 = 0.f, m10 = 0.f, m11 = 0.f;
            if (g1 < NK) {
                float2 ma = *(const float2*)(mrow0 + g0); m00 = ma.x; m01 = ma.y;
                float2 mb2 = *(const float2*)(mrow1 + g0); m10 = mb2.x; m11 = mb2.y;
            } else if (g0 < NK) {
                m00 = mrow0[g0]; m10 = mrow1[g0];
            }
            float w0 = 0.f, w1 = 0.f, w2 = 0.f, w3 = 0.f;
            if (g0 < NK) {
                bool cls = g0 < CLSN;
                if (m00 >= 0.3f) w0 = exp01(__expf(c[0] * ATT_SCALE) * (cls ? iza0 : izb0));
                if (m10 >= 0.3f) w2 = exp01(__expf(c[2] * ATT_SCALE) * (cls ? iza1 : izb1));
            }
            if (g1 < NK) {
                bool cls = g1 < CLSN;
                if (m01 >= 0.3f) w1 = exp01(__expf(c[1] * ATT_SCALE) * (cls ? iza0 : izb0));
                if (m11 >= 0.3f) w3 = exp01(__expf(c[3] * ATT_SCALE) * (cls ? iza1 : izb1));
            }
            ws0 += w0 + w1;
            ws1 += w2 + w3;
            float u0 = __shfl_sync(~0u, w0, s0);
            float u1 = __shfl_sync(~0u, w1, s0);
            float u2 = __shfl_sync(~0u, w2, s0);
            float u3 = __shfl_sync(~0u, w3, s0);
            float v0 = __shfl_sync(~0u, w0, s1);
            float v1 = __shfl_sync(~0u, w1, s1);
            float v2 = __shfl_sync(~0u, w2, s1);
            float v3 = __shfl_sync(~0u, w3, s1);
            unsigned wa[4];
            wa[0] = __float_as_uint((q4 & 1) ? u1 : u0);
            wa[1] = __float_as_uint((q4 & 1) ? u3 : u2);
            wa[2] = __float_as_uint((q4 & 1) ? v1 : v0);
            wa[3] = __float_as_uint((q4 & 1) ? v3 : v2);
#pragma unroll
            for (int nn2 = 0; nn2 < 4; nn2++) {
                unsigned b0 = __float_as_uint(Vs[nn * 8 + q4][nn2 * 8 + gr]);
                unsigned b1 = __float_as_uint(Vs[nn * 8 + q4 + 4][nn2 * 8 + gr]);
                mma_tf32(av[nn2], wa, b0, b1);
            }
        }
    }
#pragma unroll
    for (int o = 1; o <= 2; o <<= 1) {
        ws0 += __shfl_xor_sync(~0u, ws0, o);
        ws1 += __shfl_xor_sync(~0u, ws1, o);
    }
    const float inv0 = 1.f / ws0;
    const float inv1 = 1.f / ws1;

    float* ob0 = O + ((size_t)(b * NT + m0 + w * 16 + gr)) * 256 + h * HD;
    float* ob1 = ob0 + (size_t)8 * 256;
#pragma unroll
    for (int nn2 = 0; nn2 < 4; nn2++) {
        *(float2*)(ob0 + nn2 * 8 + 2 * q4) = make_float2(av[nn2][0] * inv0, av[nn2][1] * inv0);
        *(float2*)(ob1 + nn2 * 8 + 2 * q4) = make_float2(av[nn2][2] * inv1, av[nn2][3] * inv1);
    }
}

// ---------------------------------------------------------------------------
// (B, T, C) -> (B, C, H, W) transpose
// ---------------------------------------------------------------------------
__global__ __launch_bounds__(256) void transpose_k(
    const float* __restrict__ Y, float* __restrict__ O)
{
    __shared__ float t[32][33];
    const int b = blockIdx.z;
    const int t0 = blockIdx.x * 32;
    const int c0 = blockIdx.y * 32;
    for (int i = threadIdx.y; i < 32; i += 8)
        t[i][threadIdx.x] = Y[((size_t)(b * NT + t0 + i)) * 256 + c0 + threadIdx.x];
    __syncthreads();
    for (int i = threadIdx.y; i < 32; i += 8)
        O[((size_t)(b * 256 + c0 + i)) * NT + t0 + threadIdx.x] = t[threadIdx.x][i];
}

// ---------------------------------------------------------------------------
extern "C" void kernel_launch(void* const* d_in, const int* in_sizes, int n_in,
                              void* d_out, int out_size)
{
    const float* x_query = (const float*)d_in[0];
    const float* x_key   = (const float*)d_in[1];
    const float* mask_u  = (const float*)d_in[2];
    const float* g1  = (const float*)d_in[3];
    const float* be1 = (const float*)d_in[4];
    const float* g2  = (const float*)d_in[5];
    const float* be2 = (const float*)d_in[6];
    const float* g3  = (const float*)d_in[7];
    const float* be3 = (const float*)d_in[8];
    const float* Wq  = (const float*)d_in[9];
    const float* Wkv = (const float*)d_in[10];
    // d_in[11] = Wcls: dead code (outputs sliced away by x[:, CLS:])
    const float* Wp  = (const float*)d_in[12];
    const float* bp  = (const float*)d_in[13];
    const float* W1  = (const float*)d_in[14];
    const float* bf1 = (const float*)d_in[15];
    const float* W2  = (const float*)d_in[16];
    const float* bf2 = (const float*)d_in[17];
    float* out = (float*)d_out;

    static float *xq = nullptr, *qin, *kin, *q, *kv, *ao, *x2, *ln3, *hbuf, *y;
    if (!xq) {
        cudaGetSymbolAddress((void**)&xq,   g_xq);
        cudaGetSymbolAddress((void**)&qin,  g_qin);
        cudaGetSymbolAddress((void**)&kin,  g_kin);
        cudaGetSymbolAddress((void**)&q,    g_q);
        cudaGetSymbolAddress((void**)&kv,   g_kv);
        cudaGetSymbolAddress((void**)&ao,   g_ao);
        cudaGetSymbolAddress((void**)&x2,   g_x2);
        cudaGetSymbolAddress((void**)&ln3,  g_ln3);
        cudaGetSymbolAddress((void**)&hbuf, g_h);
        cudaGetSymbolAddress((void**)&y,    g_y);
    }

    // 1. LN(x_query) with NCHW gather; writes xq (residual) + qin
    ln_q_kernel<<<dim3(NT / 32, BB), 256>>>(x_query, g1, be1, xq, qin);
    // 2. LN(x_key) -> kin
    ln_row_kernel<<<(KTOT + 7) / 8, 256>>>(x_key, g2, be2, kin, KTOT);
    // 3. Q = qin @ Wq
    gemm_mma<false, false, false><<<dim3(4, (MTOT + 127) / 128), 256>>>(
        qin, Wq, nullptr, nullptr, q, MTOT, 256, 256);
    // 4. KV = kin @ Wkv
    gemm_mma<false, false, false><<<dim3(8, (KTOT + 127) / 128), 256>>>(
        kin, Wkv, nullptr, nullptr, kv, KTOT, 512, 256);
    // 5. attention (tensor-core tf32) -> ao
    attn_mma_kernel<<<dim3(NT / 128, HDS, BB), 256>>>(q, kv, mask_u, ao);
    // 6. x2 = xq + (ao @ Wp + bp)
    gemm_mma<true, true, false><<<dim3(4, (MTOT + 127) / 128), 256>>>(
        ao, Wp, bp, xq, x2, MTOT, 256, 256);
    // 7. ln3 = LN(x2)
    ln_row_kernel<<<(MTOT + 7) / 8, 256>>>(x2, g3, be3, ln3, MTOT);
    // 8. h = gelu(ln3 @ W1 + bf1)
    gemm_mma<true, false, true><<<dim3(16, (MTOT + 127) / 128), 256>>>(
        ln3, W1, bf1, nullptr, hbuf, MTOT, 1024, 256);
    // 9. y = x2 + (h @ W2 + bf2)
    gemm_mma<true, true, false><<<dim3(4, (MTOT + 127) / 128), 256>>>(
        hbuf, W2, bf2, x2, y, MTOT, 256, 1024);
    // 10. transpose to (B, C, H, W)
    transpose_k<<<dim3(NT / 32, 256 / 32, BB), dim3(32, 8)>>>(y, out);
}

// round 11
// speedup vs baseline: 2.1304x; 1.0839x over previous
#include <cuda_runtime.h>
#include <math.h>

#define BB   2
#define CC   256
#define NT   2304      // 48*48
#define NK   2324      // CLS + NT
#define CLSN 20
#define HDS  8
#define HD   32
#define MTOT (BB*NT)   // 4608
#define KTOT (BB*NK)   // 4648
#define ATT_SCALE 0.17677669529663687f

__device__ float g_xq  [MTOT*CC];
__device__ float g_qin [MTOT*CC];
__device__ float g_kin [KTOT*CC];
__device__ float g_q   [MTOT*CC];
__device__ float g_kv  [KTOT*2*CC];
__device__ float g_ao  [MTOT*CC];
__device__ float g_x2  [MTOT*CC];
__device__ float g_ln3 [MTOT*CC];
__device__ float g_h   [MTOT*4*CC];
__device__ float g_y   [MTOT*CC];

// ---------------------------------------------------------------------------
// tf32 tensor-core MMA: D(16x8) += A(16x8) @ B(8x8)
// ---------------------------------------------------------------------------
__device__ __forceinline__ void mma_tf32(float c[4], const unsigned a[4],
                                         unsigned b0, unsigned b1)
{
    asm volatile(
        "mma.sync.aligned.m16n8k8.row.col.f32.tf32.tf32.f32 "
        "{%0,%1,%2,%3}, {%4,%5,%6,%7}, {%8,%9}, {%0,%1,%2,%3};"
        : "+f"(c[0]), "+f"(c[1]), "+f"(c[2]), "+f"(c[3])
        : "r"(a[0]), "r"(a[1]), "r"(a[2]), "r"(a[3]), "r"(b0), "r"(b1));
}

__device__ __forceinline__ void cp16(void* smem_dst, const void* gmem_src)
{
    unsigned dst = (unsigned)__cvta_generic_to_shared(smem_dst);
    asm volatile("cp.async.ca.shared.global [%0], [%1], 16;" :: "r"(dst), "l"(gmem_src));
}
#define CP_COMMIT() asm volatile("cp.async.commit_group;")
#define CP_WAIT1()  asm volatile("cp.async.wait_group 1;")

// exp(p) for p in [0, ~1.1] — degree-6 Taylor about 0.5, rel err < 3e-6 (FMA only).
__device__ __forceinline__ float exp01(float p)
{
    float r = p - 0.5f;
    float q = 1.f + r * (1.f + r * (0.5f + r * (0.16666667f +
              r * (0.041666667f + r * (0.0083333333f + r * 0.0013888889f)))));
    return 1.6487212707001282f * q;
}

// ---------------------------------------------------------------------------
// LN over x_query with NCHW -> (B, T, C) gather. Block = 32 t-rows.
// ---------------------------------------------------------------------------
__global__ __launch_bounds__(256) void ln_q_kernel(
    const float* __restrict__ X, const float* __restrict__ g1,
    const float* __restrict__ be1, float* __restrict__ XQ, float* __restrict__ QIN)
{
    __shared__ float s[32][257];
    const int b = blockIdx.y;
    const int t0 = blockIdx.x * 32;
    const int tw = threadIdx.x & 31;
    const int tc = threadIdx.x >> 5;
    for (int c0 = 0; c0 < 256; c0 += 8) {
        int c = c0 + tc;
        s[tw][c] = X[((size_t)(b * 256 + c)) * NT + t0 + tw];
    }
    __syncthreads();
    const int warp = threadIdx.x >> 5, lane = threadIdx.x & 31;
    for (int r = warp * 4; r < warp * 4 + 4; r++) {
        float v[8];
        float sum = 0.f, ss = 0.f;
#pragma unroll
        for (int u = 0; u < 8; u++) { float x = s[r][lane + 32 * u]; v[u] = x; sum += x; ss += x * x; }
#pragma unroll
        for (int o = 16; o; o >>= 1) {
            sum += __shfl_xor_sync(~0u, sum, o);
            ss  += __shfl_xor_sync(~0u, ss, o);
        }
        float mean = sum * (1.f / 256.f);
        float var  = ss * (1.f / 256.f) - mean * mean;
        float rs   = rsqrtf(var + 1e-5f);
        size_t base = ((size_t)(b * NT + t0 + r)) * 256;
#pragma unroll
        for (int u = 0; u < 8; u++) {
            int c = lane + 32 * u;
            XQ [base + c] = v[u];
            QIN[base + c] = (v[u] - mean) * rs * g1[c] + be1[c];
        }
    }
}

// ---------------------------------------------------------------------------
// LN over contiguous 256-wide rows. One warp per row.
// ---------------------------------------------------------------------------
__global__ __launch_bounds__(256) void ln_row_kernel(
    const float* __restrict__ X, const float* __restrict__ g,
    const float* __restrict__ be, float* __restrict__ Y, int rows)
{
    int w = (blockIdx.x * blockDim.x + threadIdx.x) >> 5;
    int lane = threadIdx.x & 31;
    if (w >= rows) return;
    const float* x = X + (size_t)w * 256;
    float4 v0 = *(const float4*)(x + lane * 4);
    float4 v1 = *(const float4*)(x + 128 + lane * 4);
    float sum = v0.x + v0.y + v0.z + v0.w + v1.x + v1.y + v1.z + v1.w;
    float ss  = v0.x*v0.x + v0.y*v0.y + v0.z*v0.z + v0.w*v0.w
              + v1.x*v1.x + v1.y*v1.y + v1.z*v1.z + v1.w*v1.w;
#pragma unroll
    for (int o = 16; o; o >>= 1) {
        sum += __shfl_xor_sync(~0u, sum, o);
        ss  += __shfl_xor_sync(~0u, ss, o);
    }
    float mean = sum * (1.f / 256.f);
    float var  = ss * (1.f / 256.f) - mean * mean;
    float rs   = rsqrtf(var + 1e-5f);
    float* y = Y + (size_t)w * 256;
    int c0 = lane * 4;
    float4 ga = *(const float4*)(g + c0),  ba = *(const float4*)(be + c0);
    float4 gb = *(const float4*)(g + 128 + c0), bb = *(const float4*)(be + 128 + c0);
    float4 o0, o1;
    o0.x = (v0.x - mean) * rs * ga.x + ba.x;
    o0.y = (v0.y - mean) * rs * ga.y + ba.y;
    o0.z = (v0.z - mean) * rs * ga.z + ba.z;
    o0.w = (v0.w - mean) * rs * ga.w + ba.w;
    o1.x = (v1.x - mean) * rs * gb.x + bb.x;
    o1.y = (v1.y - mean) * rs * gb.y + bb.y;
    o1.z = (v1.z - mean) * rs * gb.z + bb.z;
    o1.w = (v1.w - mean) * rs * gb.w + bb.w;
    *(float4*)(y + c0) = o0;
    *(float4*)(y + 128 + c0) = o1;
}

// ---------------------------------------------------------------------------
// tf32 tensor-core GEMM, double-buffered cp.async staging.
// BM=128, BN=64, BK=16; 8 warps, warp tile 32x32.
// ---------------------------------------------------------------------------
template<bool BIAS, bool RES, bool GELU>
__global__ __launch_bounds__(256, 2) void gemm_mma(
    const float* __restrict__ A, const float* __restrict__ W,
    const float* __restrict__ bias, const float* __restrict__ Res,
    float* __restrict__ C, int M, int N, int K)
{
    __shared__ float As[2][128][36];
    __shared__ float Bs[2][16][72];
    const int n0 = blockIdx.x * 64;
    const int m0 = blockIdx.y * 128;
    const int tid  = threadIdx.x;
    const int w    = tid >> 5;
    const int lane = tid & 31;
    const int wm = (w & 3) * 32;
    const int wn = (w >> 2) * 32;
    const int gr = lane >> 2, q4 = lane & 3;

    float acc[2][4][4];
#pragma unroll
    for (int mi = 0; mi < 2; mi++)
#pragma unroll
        for (int ni = 0; ni < 4; ni++)
#pragma unroll
            for (int j = 0; j < 4; j++) acc[mi][ni][j] = 0.f;

    const int ar  = tid >> 2;
    const int ac4 = tid & 3;
    const int bk  = tid >> 4;
    const int bc4 = tid & 15;

    const int KT = K >> 4;

    // stage(s, k0)
    auto stage = [&](int s, int k0) {
#pragma unroll
        for (int l = 0; l < 2; l++) {
            int row = ar + l * 64;
            if (m0 + row < M)
                cp16(&As[s][row][ac4 * 4], A + (size_t)(m0 + row) * K + k0 + ac4 * 4);
            else
                *(float4*)&As[s][row][ac4 * 4] = make_float4(0.f, 0.f, 0.f, 0.f);
        }
        cp16(&Bs[s][bk][bc4 * 4], W + (size_t)(k0 + bk) * N + n0 + bc4 * 4);
    };

    stage(0, 0);
    CP_COMMIT();

    for (int kt = 0; kt < KT; kt++) {
        if (kt + 1 < KT) stage((kt + 1) & 1, (kt + 1) * 16);
        CP_COMMIT();
        CP_WAIT1();
        __syncthreads();
        const int buf = kt & 1;
#pragma unroll
        for (int kk = 0; kk < 2; kk++) {
            unsigned a[2][4];
#pragma unroll
            for (int mi = 0; mi < 2; mi++) {
                int rb = wm + mi * 16;
                a[mi][0] = __float_as_uint(As[buf][rb + gr    ][kk * 8 + q4]);
                a[mi][1] = __float_as_uint(As[buf][rb + gr + 8][kk * 8 + q4]);
                a[mi][2] = __float_as_uint(As[buf][rb + gr    ][kk * 8 + q4 + 4]);
                a[mi][3] = __float_as_uint(As[buf][rb + gr + 8][kk * 8 + q4 + 4]);
            }
#pragma unroll
            for (int ni = 0; ni < 4; ni++) {
                unsigned b0 = __float_as_uint(Bs[buf][kk * 8 + q4    ][wn + ni * 8 + gr]);
                unsigned b1 = __float_as_uint(Bs[buf][kk * 8 + q4 + 4][wn + ni * 8 + gr]);
#pragma unroll
                for (int mi = 0; mi < 2; mi++)
                    mma_tf32(acc[mi][ni], a[mi], b0, b1);
            }
        }
        __syncthreads();
    }

#pragma unroll
    for (int mi = 0; mi < 2; mi++) {
        int row0 = m0 + wm + mi * 16 + gr;
        int row1 = row0 + 8;
#pragma unroll
        for (int ni = 0; ni < 4; ni++) {
            int cn = n0 + wn + ni * 8 + 2 * q4;
            float b0v = 0.f, b1v = 0.f;
            if (BIAS) { b0v = bias[cn]; b1v = bias[cn + 1]; }
#pragma unroll
            for (int half = 0; half < 2; half++) {
                int r = half ? row1 : row0;
                if (r >= M) continue;
                float v0 = acc[mi][ni][half * 2 + 0] + b0v;
                float v1 = acc[mi][ni][half * 2 + 1] + b1v;
                if (GELU) {
                    v0 = 0.5f * v0 * (1.f + erff(v0 * 0.70710678118654752f));
                    v1 = 0.5f * v1 * (1.f + erff(v1 * 0.70710678118654752f));
                }
                if (RES) {
                    v0 += Res[(size_t)r * N + cn];
                    v1 += Res[(size_t)r * N + cn + 1];
                }
                *(float2*)(C + (size_t)r * N + cn) = make_float2(v0, v1);
            }
        }
    }
}

// ---------------------------------------------------------------------------
// Tensor-core attention v2. Block = 256 query rows of one (b,h); 8 warps,
// each warp 32 rows = 2 m16 fragments (B-frag LDS reused 2x). Double-buffered
// cp.async K/V staging. Grid (9, 8, 2) = 144 ~= 1 CTA/SM.
// ---------------------------------------------------------------------------
__global__ __launch_bounds__(256) void attn_mma_kernel(
    const float* __restrict__ Q, const float* __restrict__ KV,
    const float* __restrict__ MU, float* __restrict__ O)
{
    const int m0 = blockIdx.x * 256;
    const int h  = blockIdx.y;
    const int b  = blockIdx.z;
    const int tid  = threadIdx.x;
    const int w    = tid >> 5;
    const int lane = tid & 31;
    const int gr   = lane >> 2;
    const int q4   = lane & 3;

    __shared__ float Ks[2][64][36];
    __shared__ float Vs[2][64][36];

    // Q fragments: 2 m-frags; rows m0+w*32+mi*16+gr(+8), cols h*32+kk*8+q4(+4)
    unsigned qa[2][4][4];
    {
        const float* qb = Q + ((size_t)(b * NT + m0 + w * 32)) * 256 + h * HD;
#pragma unroll
        for (int mi = 0; mi < 2; mi++)
#pragma unroll
            for (int kk = 0; kk < 4; kk++) {
                const float* r0 = qb + (size_t)(mi * 16 + gr) * 256;
                const float* r1 = r0 + 8 * 256;
                qa[mi][kk][0] = __float_as_uint(r0[kk * 8 + q4]);
                qa[mi][kk][1] = __float_as_uint(r1[kk * 8 + q4]);
                qa[mi][kk][2] = __float_as_uint(r0[kk * 8 + q4 + 4]);
                qa[mi][kk][3] = __float_as_uint(r1[kk * 8 + q4 + 4]);
            }
    }

    const float* kb = KV + (size_t)b * NK * 512 + h * HD;
    const float* vb = kb + 256;

    const int lr = tid >> 3;        // 0..31 — used with f layout below
    const int lc = tid & 7;

    // ---- pass A: per-segment exp sums. z[frag][rowhalf][seg] ----
    float z[2][2][2] = {{{0.f,0.f},{0.f,0.f}},{{0.f,0.f},{0.f,0.f}}};

    // stage K tile
    auto stageK = [&](int s, int cb) {
        int nv = min(64, NK - cb);
#pragma unroll
        for (int l = 0; l < 2; l++) {
            int r = lr + l * 32;
            if (r < nv) cp16(&Ks[s][r][lc * 4], kb + (size_t)(cb + r) * 512 + lc * 4);
            else        *(float4*)&Ks[s][r][lc * 4] = make_float4(0.f, 0.f, 0.f, 0.f);
        }
    };
    auto stageV = [&](int s, int cb) {
        int nv = min(64, NK - cb);
#pragma unroll
        for (int l = 0; l < 2; l++) {
            int r = lr + l * 32;
            if (r < nv) cp16(&Vs[s][r][lc * 4], vb + (size_t)(cb + r) * 512 + lc * 4);
            else        *(float4*)&Vs[s][r][lc * 4] = make_float4(0.f, 0.f, 0.f, 0.f);
        }
    };

    stageK(0, 0);
    CP_COMMIT();
    for (int t = 0; t < 37; t++) {
        const int cb = t * 64;
        if (t + 1 < 37) stageK((t + 1) & 1, cb + 64);
        CP_COMMIT();
        CP_WAIT1();
        __syncthreads();
        const float (*K_)[36] = Ks[t & 1];
#pragma unroll
        for (int nn = 0; nn < 8; nn++) {
            float c0[4] = {0.f,0.f,0.f,0.f}, c1[4] = {0.f,0.f,0.f,0.f};
#pragma unroll
            for (int kk = 0; kk < 4; kk++) {
                unsigned b0 = __float_as_uint(K_[nn * 8 + gr][kk * 8 + q4]);
                unsigned b1 = __float_as_uint(K_[nn * 8 + gr][kk * 8 + q4 + 4]);
                mma_tf32(c0, qa[0][kk], b0, b1);
                mma_tf32(c1, qa[1][kk], b0, b1);
            }
            const int g0 = cb + nn * 8 + 2 * q4;
            // g0 even, NK & CLSN even -> g0 and g0+1 share bounds & segment
            if (g0 < NK) {
                int sg = (g0 < CLSN) ? 0 : 1;
                z[0][0][sg] += __expf(c0[0] * ATT_SCALE) + __expf(c0[1] * ATT_SCALE);
                z[0][1][sg] += __expf(c0[2] * ATT_SCALE) + __expf(c0[3] * ATT_SCALE);
                z[1][0][sg] += __expf(c1[0] * ATT_SCALE) + __expf(c1[1] * ATT_SCALE);
                z[1][1][sg] += __expf(c1[2] * ATT_SCALE) + __expf(c1[3] * ATT_SCALE);
            }
        }
        __syncthreads();
    }
    // quad all-reduce -> reciprocals
    float iz[2][2][2];
#pragma unroll
    for (int mi = 0; mi < 2; mi++)
#pragma unroll
        for (int rh = 0; rh < 2; rh++)
#pragma unroll
            for (int sg = 0; sg < 2; sg++) {
                float v = z[mi][rh][sg];
                v += __shfl_xor_sync(~0u, v, 1);
                v += __shfl_xor_sync(~0u, v, 2);
                iz[mi][rh][sg] = 1.f / v;
            }

    // ---- pass B ----
    float av[2][4][4];
#pragma unroll
    for (int mi = 0; mi < 2; mi++)
#pragma unroll
        for (int ni = 0; ni < 4; ni++)
#pragma unroll
            for (int j = 0; j < 4; j++) av[mi][ni][j] = 0.f;
    float ws[2][2] = {{0.f,0.f},{0.f,0.f}};

    const float* mbase = MU + (((size_t)(b * HDS + h)) * NK + CLSN + m0 + w * 32 + gr) * NK;
    const int base = lane & ~3;
    const int s0 = base + (q4 >> 1);
    const int s1 = s0 + 2;

    stageK(0, 0);
    stageV(0, 0);
    CP_COMMIT();
    for (int t = 0; t < 37; t++) {
        const int cb = t * 64;
        if (t + 1 < 37) { stageK((t + 1) & 1, cb + 64); stageV((t + 1) & 1, cb + 64); }
        CP_COMMIT();
        CP_WAIT1();
        __syncthreads();
        const float (*K_)[36] = Ks[t & 1];
        const float (*V_)[36] = Vs[t & 1];
#pragma unroll
        for (int nn = 0; nn < 8; nn++) {
            float c0[4] = {0.f,0.f,0.f,0.f}, c1[4] = {0.f,0.f,0.f,0.f};
#pragma unroll
            for (int kk = 0; kk < 4; kk++) {
                unsigned b0 = __float_as_uint(K_[nn * 8 + gr][kk * 8 + q4]);
                unsigned b1 = __float_as_uint(K_[nn * 8 + gr][kk * 8 + q4 + 4]);
                mma_tf32(c0, qa[0][kk], b0, b1);
                mma_tf32(c1, qa[1][kk], b0, b1);
            }
            const int g0 = cb + nn * 8 + 2 * q4;
            float wv[2][4] = {{0.f,0.f,0.f,0.f},{0.f,0.f,0.f,0.f}};
            if (g0 < NK) {
                const int sg = (g0 < CLSN) ? 0 : 1;
                float2 mk00 = *(const float2*)(mbase + (size_t)0  * NK + g0);
                float2 mk01 = *(const float2*)(mbase + (size_t)8  * NK + g0);
                float2 mk10 = *(const float2*)(mbase + (size_t)16 * NK + g0);
                float2 mk11 = *(const float2*)(mbase + (size_t)24 * NK + g0);
                if (mk00.x >= 0.3f) wv[0][0] = exp01(__expf(c0[0] * ATT_SCALE) * iz[0][0][sg]);
                if (mk00.y >= 0.3f) wv[0][1] = exp01(__expf(c0[1] * ATT_SCALE) * iz[0][0][sg]);
                if (mk01.x >= 0.3f) wv[0][2] = exp01(__expf(c0[2] * ATT_SCALE) * iz[0][1][sg]);
                if (mk01.y >= 0.3f) wv[0][3] = exp01(__expf(c0[3] * ATT_SCALE) * iz[0][1][sg]);
                if (mk10.x >= 0.3f) wv[1][0] = exp01(__expf(c1[0] * ATT_SCALE) * iz[1][0][sg]);
                if (mk10.y >= 0.3f) wv[1][1] = exp01(__expf(c1[1] * ATT_SCALE) * iz[1][0][sg]);
                if (mk11.x >= 0.3f) wv[1][2] = exp01(__expf(c1[2] * ATT_SCALE) * iz[1][1][sg]);
                if (mk11.y >= 0.3f) wv[1][3] = exp01(__expf(c1[3] * ATT_SCALE) * iz[1][1][sg]);
            }
            ws[0][0] += wv[0][0] + wv[0][1];
            ws[0][1] += wv[0][2] + wv[0][3];
            ws[1][0] += wv[1][0] + wv[1][1];
            ws[1][1] += wv[1][2] + wv[1][3];
            // C->A fragment conversion per frag (unconditional shuffles)
            unsigned wa[2][4];
#pragma unroll
            for (int mi = 0; mi < 2; mi++) {
                float u0 = __shfl_sync(~0u, wv[mi][0], s0);
                float u1 = __shfl_sync(~0u, wv[mi][1], s0);
                float u2 = __shfl_sync(~0u, wv[mi][2], s0);
                float u3 = __shfl_sync(~0u, wv[mi][3], s0);
                float v0 = __shfl_sync(~0u, wv[mi][0], s1);
                float v1 = __shfl_sync(~0u, wv[mi][1], s1);
                float v2 = __shfl_sync(~0u, wv[mi][2], s1);
                float v3 = __shfl_sync(~0u, wv[mi][3], s1);
                wa[mi][0] = __float_as_uint((q4 & 1) ? u1 : u0);
                wa[mi][1] = __float_as_uint((q4 & 1) ? u3 : u2);
                wa[mi][2] = __float_as_uint((q4 & 1) ? v1 : v0);
                wa[mi][3] = __float_as_uint((q4 & 1) ? v3 : v2);
            }
#pragma unroll
            for (int nn2 = 0; nn2 < 4; nn2++) {
                unsigned b0 = __float_as_uint(V_[nn * 8 + q4    ][nn2 * 8 + gr]);
                unsigned b1 = __float_as_uint(V_[nn * 8 + q4 + 4][nn2 * 8 + gr]);
                mma_tf32(av[0][nn2], wa[0], b0, b1);
                mma_tf32(av[1][nn2], wa[1], b0, b1);
            }
        }
        __syncthreads();
    }
    // wsum quad all-reduce + output
#pragma unroll
    for (int mi = 0; mi < 2; mi++) {
        float w0 = ws[mi][0], w1 = ws[mi][1];
        w0 += __shfl_xor_sync(~0u, w0, 1); w0 += __shfl_xor_sync(~0u, w0, 2);
        w1 += __shfl_xor_sync(~0u, w1, 1); w1 += __shfl_xor_sync(~0u, w1, 2);
        const float inv0 = 1.f / w0;
        const float inv1 = 1.f / w1;
        float* ob0 = O + ((size_t)(b * NT + m0 + w * 32 + mi * 16 + gr)) * 256 + h * HD;
        float* ob1 = ob0 + (size_t)8 * 256;
#pragma unroll
        for (int nn2 = 0; nn2 < 4; nn2++) {
            *(float2*)(ob0 + nn2 * 8 + 2 * q4) =
                make_float2(av[mi][nn2][0] * inv0, av[mi][nn2][1] * inv0);
            *(float2*)(ob1 + nn2 * 8 + 2 * q4) =
                make_float2(av[mi][nn2][2] * inv1, av[mi][nn2][3] * inv1);
        }
    }
}

// ---------------------------------------------------------------------------
// (B, T, C) -> (B, C, H, W) transpose
// ---------------------------------------------------------------------------
__global__ __launch_bounds__(256) void transpose_k(
    const float* __restrict__ Y, float* __restrict__ O)
{
    __shared__ float t[32][33];
    const int b = blockIdx.z;
    const int t0 = blockIdx.x * 32;
    const int c0 = blockIdx.y * 32;
    for (int i = threadIdx.y; i < 32; i += 8)
        t[i][threadIdx.x] = Y[((size_t)(b * NT + t0 + i)) * 256 + c0 + threadIdx.x];
    __syncthreads();
    for (int i = threadIdx.y; i < 32; i += 8)
        O[((size_t)(b * 256 + c0 + i)) * NT + t0 + threadIdx.x] = t[threadIdx.x][i];
}

// ---------------------------------------------------------------------------
extern "C" void kernel_launch(void* const* d_in, const int* in_sizes, int n_in,
                              void* d_out, int out_size)
{
    const float* x_query = (const float*)d_in[0];
    const float* x_key   = (const float*)d_in[1];
    const float* mask_u  = (const float*)d_in[2];
    const float* g1  = (const float*)d_in[3];
    const float* be1 = (const float*)d_in[4];
    const float* g2  = (const float*)d_in[5];
    const float* be2 = (const float*)d_in[6];
    const float* g3  = (const float*)d_in[7];
    const float* be3 = (const float*)d_in[8];
    const float* Wq  = (const float*)d_in[9];
    const float* Wkv = (const float*)d_in[10];
    // d_in[11] = Wcls: dead code (outputs sliced away by x[:, CLS:])
    const float* Wp  = (const float*)d_in[12];
    const float* bp  = (const float*)d_in[13];
    const float* W1  = (const float*)d_in[14];
    const float* bf1 = (const float*)d_in[15];
    const float* W2  = (const float*)d_in[16];
    const float* bf2 = (const float*)d_in[17];
    float* out = (float*)d_out;

    static float *xq = nullptr, *qin, *kin, *q, *kv, *ao, *x2, *ln3, *hbuf, *y;
    if (!xq) {
        cudaGetSymbolAddress((void**)&xq,   g_xq);
        cudaGetSymbolAddress((void**)&qin,  g_qin);
        cudaGetSymbolAddress((void**)&kin,  g_kin);
        cudaGetSymbolAddress((void**)&q,    g_q);
        cudaGetSymbolAddress((void**)&kv,   g_kv);
        cudaGetSymbolAddress((void**)&ao,   g_ao);
        cudaGetSymbolAddress((void**)&x2,   g_x2);
        cudaGetSymbolAddress((void**)&ln3,  g_ln3);
        cudaGetSymbolAddress((void**)&hbuf, g_h);
        cudaGetSymbolAddress((void**)&y,    g_y);
    }

    // 1. LN(x_query) with NCHW gather; writes xq (residual) + qin
    ln_q_kernel<<<dim3(NT / 32, BB), 256>>>(x_query, g1, be1, xq, qin);
    // 2. LN(x_key) -> kin
    ln_row_kernel<<<(KTOT + 7) / 8, 256>>>(x_key, g2, be2, kin, KTOT);
    // 3. Q = qin @ Wq
    gemm_mma<false, false, false><<<dim3(4, (MTOT + 127) / 128), 256>>>(
        qin, Wq, nullptr, nullptr, q, MTOT, 256, 256);
    // 4. KV = kin @ Wkv
    gemm_mma<false, false, false><<<dim3(8, (KTOT + 127) / 128), 256>>>(
        kin, Wkv, nullptr, nullptr, kv, KTOT, 512, 256);
    // 5. attention (tensor-core tf32, double-buffered) -> ao
    attn_mma_kernel<<<dim3(NT / 256, HDS, BB), 256>>>(q, kv, mask_u, ao);
    // 6. x2 = xq + (ao @ Wp + bp)
    gemm_mma<true, true, false><<<dim3(4, (MTOT + 127) / 128), 256>>>(
        ao, Wp, bp, xq, x2, MTOT, 256, 256);
    // 7. ln3 = LN(x2)
    ln_row_kernel<<<(MTOT + 7) / 8, 256>>>(x2, g3, be3, ln3, MTOT);
    // 8. h = gelu(ln3 @ W1 + bf1)
    gemm_mma<true, false, true><<<dim3(16, (MTOT + 127) / 128), 256>>>(
        ln3, W1, bf1, nullptr, hbuf, MTOT, 1024, 256);
    // 9. y = x2 + (h @ W2 + bf2)
    gemm_mma<true, true, false><<<dim3(4, (MTOT + 127) / 128), 256>>>(
        hbuf, W2, bf2, x2, y, MTOT, 256, 1024);
    // 10. transpose to (B, C, H, W)
    transpose_k<<<dim3(NT / 32, 256 / 32, BB), dim3(32, 8)>>>(y, out);
}

// round 13
// speedup vs baseline: 2.2110x; 1.0378x over previous
#include <cuda_runtime.h>
#include <math.h>

#define BB   2
#define CC   256
#define NT   2304      // 48*48
#define NK   2324      // CLS + NT
#define CLSN 20
#define HDS  8
#define HD   32
#define MTOT (BB*NT)   // 4608
#define KTOT (BB*NK)   // 4648
#define ATT_SCALE 0.17677669529663687f
#define ATT_SMEM (2 * 2 * 64 * 36 * 4)   // 73728 B: Ks[2][64][36] + Vs[2][64][36]

__device__ float g_xq  [MTOT*CC];
__device__ float g_qin [MTOT*CC];
__device__ float g_kin [KTOT*CC];
__device__ float g_q   [MTOT*CC];
__device__ float g_kv  [KTOT*2*CC];
__device__ float g_ao  [MTOT*CC];
__device__ float g_x2  [MTOT*CC];
__device__ float g_ln3 [MTOT*CC];
__device__ float g_h   [MTOT*4*CC];
__device__ float g_y   [MTOT*CC];

// ---------------------------------------------------------------------------
// tf32 tensor-core MMA: D(16x8) += A(16x8) @ B(8x8)
// ---------------------------------------------------------------------------
__device__ __forceinline__ void mma_tf32(float c[4], const unsigned a[4],
                                         unsigned b0, unsigned b1)
{
    asm volatile(
        "mma.sync.aligned.m16n8k8.row.col.f32.tf32.tf32.f32 "
        "{%0,%1,%2,%3}, {%4,%5,%6,%7}, {%8,%9}, {%0,%1,%2,%3};"
        : "+f"(c[0]), "+f"(c[1]), "+f"(c[2]), "+f"(c[3])
        : "r"(a[0]), "r"(a[1]), "r"(a[2]), "r"(a[3]), "r"(b0), "r"(b1));
}

__device__ __forceinline__ void cp16(void* smem_dst, const void* gmem_src)
{
    unsigned dst = (unsigned)__cvta_generic_to_shared(smem_dst);
    asm volatile("cp.async.ca.shared.global [%0], [%1], 16;" :: "r"(dst), "l"(gmem_src));
}
#define CP_COMMIT() asm volatile("cp.async.commit_group;")
#define CP_WAIT1()  asm volatile("cp.async.wait_group 1;")

// exp(p) for p in [0, ~1.1] — degree-6 Taylor about 0.5, rel err < 3e-6 (FMA only).
__device__ __forceinline__ float exp01(float p)
{
    float r = p - 0.5f;
    float q = 1.f + r * (1.f + r * (0.5f + r * (0.16666667f +
              r * (0.041666667f + r * (0.0083333333f + r * 0.0013888889f)))));
    return 1.6487212707001282f * q;
}

// ---------------------------------------------------------------------------
// LN over x_query with NCHW -> (B, T, C) gather. Block = 32 t-rows.
// ---------------------------------------------------------------------------
__global__ __launch_bounds__(256) void ln_q_kernel(
    const float* __restrict__ X, const float* __restrict__ g1,
    const float* __restrict__ be1, float* __restrict__ XQ, float* __restrict__ QIN)
{
    __shared__ float s[32][257];
    const int b = blockIdx.y;
    const int t0 = blockIdx.x * 32;
    const int tw = threadIdx.x & 31;
    const int tc = threadIdx.x >> 5;
    for (int c0 = 0; c0 < 256; c0 += 8) {
        int c = c0 + tc;
        s[tw][c] = X[((size_t)(b * 256 + c)) * NT + t0 + tw];
    }
    __syncthreads();
    const int warp = threadIdx.x >> 5, lane = threadIdx.x & 31;
    for (int r = warp * 4; r < warp * 4 + 4; r++) {
        float v[8];
        float sum = 0.f, ss = 0.f;
#pragma unroll
        for (int u = 0; u < 8; u++) { float x = s[r][lane + 32 * u]; v[u] = x; sum += x; ss += x * x; }
#pragma unroll
        for (int o = 16; o; o >>= 1) {
            sum += __shfl_xor_sync(~0u, sum, o);
            ss  += __shfl_xor_sync(~0u, ss, o);
        }
        float mean = sum * (1.f / 256.f);
        float var  = ss * (1.f / 256.f) - mean * mean;
        float rs   = rsqrtf(var + 1e-5f);
        size_t base = ((size_t)(b * NT + t0 + r)) * 256;
#pragma unroll
        for (int u = 0; u < 8; u++) {
            int c = lane + 32 * u;
            XQ [base + c] = v[u];
            QIN[base + c] = (v[u] - mean) * rs * g1[c] + be1[c];
        }
    }
}

// ---------------------------------------------------------------------------
// LN over contiguous 256-wide rows. One warp per row.
// ---------------------------------------------------------------------------
__global__ __launch_bounds__(256) void ln_row_kernel(
    const float* __restrict__ X, const float* __restrict__ g,
    const float* __restrict__ be, float* __restrict__ Y, int rows)
{
    int w = (blockIdx.x * blockDim.x + threadIdx.x) >> 5;
    int lane = threadIdx.x & 31;
    if (w >= rows) return;
    const float* x = X + (size_t)w * 256;
    float4 v0 = *(const float4*)(x + lane * 4);
    float4 v1 = *(const float4*)(x + 128 + lane * 4);
    float sum = v0.x + v0.y + v0.z + v0.w + v1.x + v1.y + v1.z + v1.w;
    float ss  = v0.x*v0.x + v0.y*v0.y + v0.z*v0.z + v0.w*v0.w
              + v1.x*v1.x + v1.y*v1.y + v1.z*v1.z + v1.w*v1.w;
#pragma unroll
    for (int o = 16; o; o >>= 1) {
        sum += __shfl_xor_sync(~0u, sum, o);
        ss  += __shfl_xor_sync(~0u, ss, o);
    }
    float mean = sum * (1.f / 256.f);
    float var  = ss * (1.f / 256.f) - mean * mean;
    float rs   = rsqrtf(var + 1e-5f);
    float* y = Y + (size_t)w * 256;
    int c0 = lane * 4;
    float4 ga = *(const float4*)(g + c0),  ba = *(const float4*)(be + c0);
    float4 gb = *(const float4*)(g + 128 + c0), bb = *(const float4*)(be + 128 + c0);
    float4 o0, o1;
    o0.x = (v0.x - mean) * rs * ga.x + ba.x;
    o0.y = (v0.y - mean) * rs * ga.y + ba.y;
    o0.z = (v0.z - mean) * rs * ga.z + ba.z;
    o0.w = (v0.w - mean) * rs * ga.w + ba.w;
    o1.x = (v1.x - mean) * rs * gb.x + bb.x;
    o1.y = (v1.y - mean) * rs * gb.y + bb.y;
    o1.z = (v1.z - mean) * rs * gb.z + bb.z;
    o1.w = (v1.w - mean) * rs * gb.w + bb.w;
    *(float4*)(y + c0) = o0;
    *(float4*)(y + 128 + c0) = o1;
}

// ---------------------------------------------------------------------------
// tf32 tensor-core GEMM, double-buffered cp.async staging.
// BM=128, BN=64, BK=16; 8 warps, warp tile 32x32.
// ---------------------------------------------------------------------------
template<bool BIAS, bool RES, bool GELU>
__global__ __launch_bounds__(256, 2) void gemm_mma(
    const float* __restrict__ A, const float* __restrict__ W,
    const float* __restrict__ bias, const float* __restrict__ Res,
    float* __restrict__ C, int M, int N, int K)
{
    __shared__ float As[2][128][36];
    __shared__ float Bs[2][16][72];
    const int n0 = blockIdx.x * 64;
    const int m0 = blockIdx.y * 128;
    const int tid  = threadIdx.x;
    const int w    = tid >> 5;
    const int lane = tid & 31;
    const int wm = (w & 3) * 32;
    const int wn = (w >> 2) * 32;
    const int gr = lane >> 2, q4 = lane & 3;

    float acc[2][4][4];
#pragma unroll
    for (int mi = 0; mi < 2; mi++)
#pragma unroll
        for (int ni = 0; ni < 4; ni++)
#pragma unroll
            for (int j = 0; j < 4; j++) acc[mi][ni][j] = 0.f;

    const int ar  = tid >> 2;
    const int ac4 = tid & 3;
    const int bk  = tid >> 4;
    const int bc4 = tid & 15;

    const int KT = K >> 4;

    auto stage = [&](int s, int k0) {
#pragma unroll
        for (int l = 0; l < 2; l++) {
            int row = ar + l * 64;
            if (m0 + row < M)
                cp16(&As[s][row][ac4 * 4], A + (size_t)(m0 + row) * K + k0 + ac4 * 4);
            else
                *(float4*)&As[s][row][ac4 * 4] = make_float4(0.f, 0.f, 0.f, 0.f);
        }
        cp16(&Bs[s][bk][bc4 * 4], W + (size_t)(k0 + bk) * N + n0 + bc4 * 4);
    };

    stage(0, 0);
    CP_COMMIT();

    for (int kt = 0; kt < KT; kt++) {
        if (kt + 1 < KT) stage((kt + 1) & 1, (kt + 1) * 16);
        CP_COMMIT();
        CP_WAIT1();
        __syncthreads();
        const int buf = kt & 1;
#pragma unroll
        for (int kk = 0; kk < 2; kk++) {
            unsigned a[2][4];
#pragma unroll
            for (int mi = 0; mi < 2; mi++) {
                int rb = wm + mi * 16;
                a[mi][0] = __float_as_uint(As[buf][rb + gr    ][kk * 8 + q4]);
                a[mi][1] = __float_as_uint(As[buf][rb + gr + 8][kk * 8 + q4]);
                a[mi][2] = __float_as_uint(As[buf][rb + gr    ][kk * 8 + q4 + 4]);
                a[mi][3] = __float_as_uint(As[buf][rb + gr + 8][kk * 8 + q4 + 4]);
            }
#pragma unroll
            for (int ni = 0; ni < 4; ni++) {
                unsigned b0 = __float_as_uint(Bs[buf][kk * 8 + q4    ][wn + ni * 8 + gr]);
                unsigned b1 = __float_as_uint(Bs[buf][kk * 8 + q4 + 4][wn + ni * 8 + gr]);
#pragma unroll
                for (int mi = 0; mi < 2; mi++)
                    mma_tf32(acc[mi][ni], a[mi], b0, b1);
            }
        }
        __syncthreads();
    }

#pragma unroll
    for (int mi = 0; mi < 2; mi++) {
        int row0 = m0 + wm + mi * 16 + gr;
        int row1 = row0 + 8;
#pragma unroll
        for (int ni = 0; ni < 4; ni++) {
            int cn = n0 + wn + ni * 8 + 2 * q4;
            float b0v = 0.f, b1v = 0.f;
            if (BIAS) { b0v = bias[cn]; b1v = bias[cn + 1]; }
#pragma unroll
            for (int half = 0; half < 2; half++) {
                int r = half ? row1 : row0;
                if (r >= M) continue;
                float v0 = acc[mi][ni][half * 2 + 0] + b0v;
                float v1 = acc[mi][ni][half * 2 + 1] + b1v;
                if (GELU) {
                    v0 = 0.5f * v0 * (1.f + erff(v0 * 0.70710678118654752f));
                    v1 = 0.5f * v1 * (1.f + erff(v1 * 0.70710678118654752f));
                }
                if (RES) {
                    v0 += Res[(size_t)r * N + cn];
                    v1 += Res[(size_t)r * N + cn + 1];
                }
                *(float2*)(C + (size_t)r * N + cn) = make_float2(v0, v1);
            }
        }
    }
}

// ---------------------------------------------------------------------------
// Tensor-core attention v3: 512 threads / 16 warps (4 per SMSP for latency
// hiding), one 16-row m-fragment per warp, CTA = 256 q-rows of one (b,h).
// Double-buffered cp.async K/V (dynamic smem, 72 KB) + depth-4 register
// prefetch pipeline for the mask stream. Grid (9, 8, 2) = 144.
// ---------------------------------------------------------------------------
__global__ __launch_bounds__(512) void attn_mma_kernel(
    const float* __restrict__ Q, const float* __restrict__ KV,
    const float* __restrict__ MU, float* __restrict__ O)
{
    extern __shared__ float sm_att[];
    float (*Ks)[64][36] = reinterpret_cast<float (*)[64][36]>(sm_att);
    float (*Vs)[64][36] = reinterpret_cast<float (*)[64][36]>(sm_att + 2 * 64 * 36);

    const int m0 = blockIdx.x * 256;
    const int h  = blockIdx.y;
    const int b  = blockIdx.z;
    const int tid  = threadIdx.x;
    const int w    = tid >> 5;          // 0..15
    const int lane = tid & 31;
    const int gr   = lane >> 2;
    const int q4   = lane & 3;

    // Q fragment: rows m0 + w*16 + gr(+8), cols h*32 + kk*8 + q4(+4)
    unsigned qa[4][4];
    {
        const float* qb = Q + ((size_t)(b * NT + m0 + w * 16)) * 256 + h * HD;
#pragma unroll
        for (int kk = 0; kk < 4; kk++) {
            qa[kk][0] = __float_as_uint(qb[(size_t)gr * 256 + kk * 8 + q4]);
            qa[kk][1] = __float_as_uint(qb[(size_t)(gr + 8) * 256 + kk * 8 + q4]);
            qa[kk][2] = __float_as_uint(qb[(size_t)gr * 256 + kk * 8 + q4 + 4]);
            qa[kk][3] = __float_as_uint(qb[(size_t)(gr + 8) * 256 + kk * 8 + q4 + 4]);
        }
    }

    const float* kb = KV + (size_t)b * NK * 512 + h * HD;
    const float* vb = kb + 256;

    const int lr = tid >> 3;    // 0..63 : one float4 per thread per tile
    const int lc = tid & 7;

    auto stageK = [&](int s, int cb) {
        int nv = NK - cb;
        if (lr < nv) cp16(&Ks[s][lr][lc * 4], kb + (size_t)(cb + lr) * 512 + lc * 4);
        else         *(float4*)&Ks[s][lr][lc * 4] = make_float4(0.f, 0.f, 0.f, 0.f);
    };
    auto stageV = [&](int s, int cb) {
        int nv = NK - cb;
        if (lr < nv) cp16(&Vs[s][lr][lc * 4], vb + (size_t)(cb + lr) * 512 + lc * 4);
        else         *(float4*)&Vs[s][lr][lc * 4] = make_float4(0.f, 0.f, 0.f, 0.f);
    };

    // ---- pass A: per-segment exp sums. z[rowhalf][seg] ----
    float z[2][2] = {{0.f, 0.f}, {0.f, 0.f}};

    stageK(0, 0);
    CP_COMMIT();
    for (int t = 0; t < 37; t++) {
        const int cb = t * 64;
        if (t + 1 < 37) stageK((t + 1) & 1, cb + 64);
        CP_COMMIT();
        CP_WAIT1();
        __syncthreads();
        const float (*K_)[36] = Ks[t & 1];
#pragma unroll
        for (int nn = 0; nn < 8; nn++) {
            float c[4] = {0.f, 0.f, 0.f, 0.f};
#pragma unroll
            for (int kk = 0; kk < 4; kk++) {
                unsigned b0 = __float_as_uint(K_[nn * 8 + gr][kk * 8 + q4]);
                unsigned b1 = __float_as_uint(K_[nn * 8 + gr][kk * 8 + q4 + 4]);
                mma_tf32(c, qa[kk], b0, b1);
            }
            const int g0 = cb + nn * 8 + 2 * q4;   // even; g0,g0+1 same seg/bounds
            if (g0 < NK) {
                int sg = (g0 < CLSN) ? 0 : 1;
                z[0][sg] += __expf(c[0] * ATT_SCALE) + __expf(c[1] * ATT_SCALE);
                z[1][sg] += __expf(c[2] * ATT_SCALE) + __expf(c[3] * ATT_SCALE);
            }
        }
        __syncthreads();
    }
    float iz[2][2];
#pragma unroll
    for (int rh = 0; rh < 2; rh++)
#pragma unroll
        for (int sg = 0; sg < 2; sg++) {
            float v = z[rh][sg];
            v += __shfl_xor_sync(~0u, v, 1);
            v += __shfl_xor_sync(~0u, v, 2);
            iz[rh][sg] = 1.f / v;
        }

    // ---- pass B ----
    float av[4][4];
#pragma unroll
    for (int i = 0; i < 4; i++)
#pragma unroll
        for (int j = 0; j < 4; j++) av[i][j] = 0.f;
    float ws0 = 0.f, ws1 = 0.f;

    const float* mrow0 = MU + (((size_t)(b * HDS + h)) * NK + CLSN + m0 + w * 16 + gr) * NK;
    const float* mrow1 = mrow0 + (size_t)8 * NK;
    const int base = lane & ~3;
    const int s0l = base + (q4 >> 1);
    const int s1l = s0l + 2;

    // depth-4 mask prefetch pipeline (statically indexed)
    float2 pmA[4], pmB[4];
    auto ldm = [&](int s, int d) {
        int off = s * 8 + 2 * q4;
        if (off < NK) {
            pmA[d] = *(const float2*)(mrow0 + off);
            pmB[d] = *(const float2*)(mrow1 + off);
        } else {
            pmA[d] = make_float2(0.f, 0.f);
            pmB[d] = make_float2(0.f, 0.f);
        }
    };
    ldm(0, 0); ldm(1, 1); ldm(2, 2); ldm(3, 3);

    stageK(0, 0);
    stageV(0, 0);
    CP_COMMIT();
    for (int t = 0; t < 37; t++) {
        const int cb = t * 64;
        if (t + 1 < 37) { stageK((t + 1) & 1, cb + 64); stageV((t + 1) & 1, cb + 64); }
        CP_COMMIT();
        CP_WAIT1();
        __syncthreads();
        const float (*K_)[36] = Ks[t & 1];
        const float (*V_)[36] = Vs[t & 1];
#pragma unroll
        for (int nn = 0; nn < 8; nn++) {
            const int step = t * 8 + nn;           // step&3 == nn&3 (t*8 % 4 == 0)
            const int d = nn & 3;
            float c[4] = {0.f, 0.f, 0.f, 0.f};
#pragma unroll
            for (int kk = 0; kk < 4; kk++) {
                unsigned b0 = __float_as_uint(K_[nn * 8 + gr][kk * 8 + q4]);
                unsigned b1 = __float_as_uint(K_[nn * 8 + gr][kk * 8 + q4 + 4]);
                mma_tf32(c, qa[kk], b0, b1);
            }
            const int g0 = cb + nn * 8 + 2 * q4;
            float wv0 = 0.f, wv1 = 0.f, wv2 = 0.f, wv3 = 0.f;
            if (g0 < NK) {
                const int sg = (g0 < CLSN) ? 0 : 1;
                if (pmA[d].x >= 0.3f) wv0 = exp01(__expf(c[0] * ATT_SCALE) * iz[0][sg]);
                if (pmA[d].y >= 0.3f) wv1 = exp01(__expf(c[1] * ATT_SCALE) * iz[0][sg]);
                if (pmB[d].x >= 0.3f) wv2 = exp01(__expf(c[2] * ATT_SCALE) * iz[1][sg]);
                if (pmB[d].y >= 0.3f) wv3 = exp01(__expf(c[3] * ATT_SCALE) * iz[1][sg]);
            }
            ldm(step + 4, d);                      // prefetch 4 steps ahead
            ws0 += wv0 + wv1;
            ws1 += wv2 + wv3;
            // C->A fragment conversion (within quad)
            float u0 = __shfl_sync(~0u, wv0, s0l);
            float u1 = __shfl_sync(~0u, wv1, s0l);
            float u2 = __shfl_sync(~0u, wv2, s0l);
            float u3 = __shfl_sync(~0u, wv3, s0l);
            float v0 = __shfl_sync(~0u, wv0, s1l);
            float v1 = __shfl_sync(~0u, wv1, s1l);
            float v2 = __shfl_sync(~0u, wv2, s1l);
            float v3 = __shfl_sync(~0u, wv3, s1l);
            unsigned wa[4];
            wa[0] = __float_as_uint((q4 & 1) ? u1 : u0);
            wa[1] = __float_as_uint((q4 & 1) ? u3 : u2);
            wa[2] = __float_as_uint((q4 & 1) ? v1 : v0);
            wa[3] = __float_as_uint((q4 & 1) ? v3 : v2);
#pragma unroll
            for (int nn2 = 0; nn2 < 4; nn2++) {
                unsigned b0 = __float_as_uint(V_[nn * 8 + q4    ][nn2 * 8 + gr]);
                unsigned b1 = __float_as_uint(V_[nn * 8 + q4 + 4][nn2 * 8 + gr]);
                mma_tf32(av[nn2], wa, b0, b1);
            }
        }
        __syncthreads();
    }
#pragma unroll
    for (int o = 1; o <= 2; o <<= 1) {
        ws0 += __shfl_xor_sync(~0u, ws0, o);
        ws1 += __shfl_xor_sync(~0u, ws1, o);
    }
    const float inv0 = 1.f / ws0;
    const float inv1 = 1.f / ws1;

    float* ob0 = O + ((size_t)(b * NT + m0 + w * 16 + gr)) * 256 + h * HD;
    float* ob1 = ob0 + (size_t)8 * 256;
#pragma unroll
    for (int nn2 = 0; nn2 < 4; nn2++) {
        *(float2*)(ob0 + nn2 * 8 + 2 * q4) = make_float2(av[nn2][0] * inv0, av[nn2][1] * inv0);
        *(float2*)(ob1 + nn2 * 8 + 2 * q4) = make_float2(av[nn2][2] * inv1, av[nn2][3] * inv1);
    }
}

// ---------------------------------------------------------------------------
// (B, T, C) -> (B, C, H, W) transpose
// ---------------------------------------------------------------------------
__global__ __launch_bounds__(256) void transpose_k(
    const float* __restrict__ Y, float* __restrict__ O)
{
    __shared__ float t[32][33];
    const int b = blockIdx.z;
    const int t0 = blockIdx.x * 32;
    const int c0 = blockIdx.y * 32;
    for (int i = threadIdx.y; i < 32; i += 8)
        t[i][threadIdx.x] = Y[((size_t)(b * NT + t0 + i)) * 256 + c0 + threadIdx.x];
    __syncthreads();
    for (int i = threadIdx.y; i < 32; i += 8)
        O[((size_t)(b * 256 + c0 + i)) * NT + t0 + threadIdx.x] = t[threadIdx.x][i];
}

// ---------------------------------------------------------------------------
extern "C" void kernel_launch(void* const* d_in, const int* in_sizes, int n_in,
                              void* d_out, int out_size)
{
    const float* x_query = (const float*)d_in[0];
    const float* x_key   = (const float*)d_in[1];
    const float* mask_u  = (const float*)d_in[2];
    const float* g1  = (const float*)d_in[3];
    const float* be1 = (const float*)d_in[4];
    const float* g2  = (const float*)d_in[5];
    const float* be2 = (const float*)d_in[6];
    const float* g3  = (const float*)d_in[7];
    const float* be3 = (const float*)d_in[8];
    const float* Wq  = (const float*)d_in[9];
    const float* Wkv = (const float*)d_in[10];
    // d_in[11] = Wcls: dead code (outputs sliced away by x[:, CLS:])
    const float* Wp  = (const float*)d_in[12];
    const float* bp  = (const float*)d_in[13];
    const float* W1  = (const float*)d_in[14];
    const float* bf1 = (const float*)d_in[15];
    const float* W2  = (const float*)d_in[16];
    const float* bf2 = (const float*)d_in[17];
    float* out = (float*)d_out;

    static float *xq = nullptr, *qin, *kin, *q, *kv, *ao, *x2, *ln3, *hbuf, *y;
    if (!xq) {
        cudaGetSymbolAddress((void**)&xq,   g_xq);
        cudaGetSymbolAddress((void**)&qin,  g_qin);
        cudaGetSymbolAddress((void**)&kin,  g_kin);
        cudaGetSymbolAddress((void**)&q,    g_q);
        cudaGetSymbolAddress((void**)&kv,   g_kv);
        cudaGetSymbolAddress((void**)&ao,   g_ao);
        cudaGetSymbolAddress((void**)&x2,   g_x2);
        cudaGetSymbolAddress((void**)&ln3,  g_ln3);
        cudaGetSymbolAddress((void**)&hbuf, g_h);
        cudaGetSymbolAddress((void**)&y,    g_y);
        cudaFuncSetAttribute(attn_mma_kernel,
                             cudaFuncAttributeMaxDynamicSharedMemorySize, ATT_SMEM);
    }

    // 1. LN(x_query) with NCHW gather; writes xq (residual) + qin
    ln_q_kernel<<<dim3(NT / 32, BB), 256>>>(x_query, g1, be1, xq, qin);
    // 2. LN(x_key) -> kin
    ln_row_kernel<<<(KTOT + 7) / 8, 256>>>(x_key, g2, be2, kin, KTOT);
    // 3. Q = qin @ Wq
    gemm_mma<false, false, false><<<dim3(4, (MTOT + 127) / 128), 256>>>(
        qin, Wq, nullptr, nullptr, q, MTOT, 256, 256);
    // 4. KV = kin @ Wkv
    gemm_mma<false, false, false><<<dim3(8, (KTOT + 127) / 128), 256>>>(
        kin, Wkv, nullptr, nullptr, kv, KTOT, 512, 256);
    // 5. attention (tf32 mma, 16 warps, mask-prefetch) -> ao
    attn_mma_kernel<<<dim3(NT / 256, HDS, BB), 512, ATT_SMEM>>>(q, kv, mask_u, ao);
    // 6. x2 = xq + (ao @ Wp + bp)
    gemm_mma<true, true, false><<<dim3(4, (MTOT + 127) / 128), 256>>>(
        ao, Wp, bp, xq, x2, MTOT, 256, 256);
    // 7. ln3 = LN(x2)
    ln_row_kernel<<<(MTOT + 7) / 8, 256>>>(x2, g3, be3, ln3, MTOT);
    // 8. h = gelu(ln3 @ W1 + bf1)
    gemm_mma<true, false, true><<<dim3(16, (MTOT + 127) / 128), 256>>>(
        ln3, W1, bf1, nullptr, hbuf, MTOT, 1024, 256);
    // 9. y = x2 + (h @ W2 + bf2)
    gemm_mma<true, true, false><<<dim3(4, (MTOT + 127) / 128), 256>>>(
        hbuf, W2, bf2, x2, y, MTOT, 256, 1024);
    // 10. transpose to (B, C, H, W)
    transpose_k<<<dim3(NT / 32, 256 / 32, BB), dim3(32, 8)>>>(y, out);
}

// round 16
// speedup vs baseline: 3.1507x; 1.4250x over previous
#include <cuda_runtime.h>
#include <math.h>

#define BB   2
#define CC   256
#define NT   2304      // 48*48
#define NK   2324      // CLS + NT
#define CLSN 20
#define HDS  8
#define HD   32
#define MTOT (BB*NT)   // 4608
#define KTOT (BB*NK)   // 4648
#define ATT_SCALE 0.17677669529663687f
#define ATT_SMEM (2 * 2 * 64 * 36 * 4)   // 73728 B: Ks[2][64][36] + Vs[2][64][36]

__device__ float g_xq  [MTOT*CC];
__device__ float g_qin [MTOT*CC];
__device__ float g_kin [KTOT*CC];
__device__ float g_q   [MTOT*CC];
__device__ float g_kv  [KTOT*2*CC];
__device__ float g_ao  [MTOT*CC];
__device__ float g_x2  [MTOT*CC];
__device__ float g_ln3 [MTOT*CC];
__device__ float g_h   [MTOT*4*CC];
__device__ float g_y   [MTOT*CC];

// ---------------------------------------------------------------------------
// tf32 tensor-core MMA: D(16x8) += A(16x8) @ B(8x8)
// ---------------------------------------------------------------------------
__device__ __forceinline__ void mma_tf32(float c[4], const unsigned a[4],
                                         unsigned b0, unsigned b1)
{
    asm volatile(
        "mma.sync.aligned.m16n8k8.row.col.f32.tf32.tf32.f32 "
        "{%0,%1,%2,%3}, {%4,%5,%6,%7}, {%8,%9}, {%0,%1,%2,%3};"
        : "+f"(c[0]), "+f"(c[1]), "+f"(c[2]), "+f"(c[3])
        : "r"(a[0]), "r"(a[1]), "r"(a[2]), "r"(a[3]), "r"(b0), "r"(b1));
}

__device__ __forceinline__ void cp16(void* smem_dst, const void* gmem_src)
{
    unsigned dst = (unsigned)__cvta_generic_to_shared(smem_dst);
    asm volatile("cp.async.ca.shared.global [%0], [%1], 16;" :: "r"(dst), "l"(gmem_src));
}
#define CP_COMMIT() asm volatile("cp.async.commit_group;")
#define CP_WAIT1()  asm volatile("cp.async.wait_group 1;")

// exp(p) for p in [0, ~1.1] — degree-6 Taylor about 0.5, rel err < 3e-6 (FMA only).
__device__ __forceinline__ float exp01(float p)
{
    float r = p - 0.5f;
    float q = 1.f + r * (1.f + r * (0.5f + r * (0.16666667f +
              r * (0.041666667f + r * (0.0083333333f + r * 0.0013888889f)))));
    return 1.6487212707001282f * q;
}

// ---------------------------------------------------------------------------
// LN over x_query with NCHW -> (B, T, C) gather. Block = 32 t-rows.
// ---------------------------------------------------------------------------
__global__ __launch_bounds__(256) void ln_q_kernel(
    const float* __restrict__ X, const float* __restrict__ g1,
    const float* __restrict__ be1, float* __restrict__ XQ, float* __restrict__ QIN)
{
    __shared__ float s[32][257];
    const int b = blockIdx.y;
    const int t0 = blockIdx.x * 32;
    const int tw = threadIdx.x & 31;
    const int tc = threadIdx.x >> 5;
    for (int c0 = 0; c0 < 256; c0 += 8) {
        int c = c0 + tc;
        s[tw][c] = X[((size_t)(b * 256 + c)) * NT + t0 + tw];
    }
    __syncthreads();
    const int warp = threadIdx.x >> 5, lane = threadIdx.x & 31;
    for (int r = warp * 4; r < warp * 4 + 4; r++) {
        float v[8];
        float sum = 0.f, ss = 0.f;
#pragma unroll
        for (int u = 0; u < 8; u++) { float x = s[r][lane + 32 * u]; v[u] = x; sum += x; ss += x * x; }
#pragma unroll
        for (int o = 16; o; o >>= 1) {
            sum += __shfl_xor_sync(~0u, sum, o);
            ss  += __shfl_xor_sync(~0u, ss, o);
        }
        float mean = sum * (1.f / 256.f);
        float var  = ss * (1.f / 256.f) - mean * mean;
        float rs   = rsqrtf(var + 1e-5f);
        size_t base = ((size_t)(b * NT + t0 + r)) * 256;
#pragma unroll
        for (int u = 0; u < 8; u++) {
            int c = lane + 32 * u;
            XQ [base + c] = v[u];
            QIN[base + c] = (v[u] - mean) * rs * g1[c] + be1[c];
        }
    }
}

// ---------------------------------------------------------------------------
// LN over contiguous 256-wide rows. One warp per row.
// ---------------------------------------------------------------------------
__global__ __launch_bounds__(256) void ln_row_kernel(
    const float* __restrict__ X, const float* __restrict__ g,
    const float* __restrict__ be, float* __restrict__ Y, int rows)
{
    int w = (blockIdx.x * blockDim.x + threadIdx.x) >> 5;
    int lane = threadIdx.x & 31;
    if (w >= rows) return;
    const float* x = X + (size_t)w * 256;
    float4 v0 = *(const float4*)(x + lane * 4);
    float4 v1 = *(const float4*)(x + 128 + lane * 4);
    float sum = v0.x + v0.y + v0.z + v0.w + v1.x + v1.y + v1.z + v1.w;
    float ss  = v0.x*v0.x + v0.y*v0.y + v0.z*v0.z + v0.w*v0.w
              + v1.x*v1.x + v1.y*v1.y + v1.z*v1.z + v1.w*v1.w;
#pragma unroll
    for (int o = 16; o; o >>= 1) {
        sum += __shfl_xor_sync(~0u, sum, o);
        ss  += __shfl_xor_sync(~0u, ss, o);
    }
    float mean = sum * (1.f / 256.f);
    float var  = ss * (1.f / 256.f) - mean * mean;
    float rs   = rsqrtf(var + 1e-5f);
    float* y = Y + (size_t)w * 256;
    int c0 = lane * 4;
    float4 ga = *(const float4*)(g + c0),  ba = *(const float4*)(be + c0);
    float4 gb = *(const float4*)(g + 128 + c0), bb = *(const float4*)(be + 128 + c0);
    float4 o0, o1;
    o0.x = (v0.x - mean) * rs * ga.x + ba.x;
    o0.y = (v0.y - mean) * rs * ga.y + ba.y;
    o0.z = (v0.z - mean) * rs * ga.z + ba.z;
    o0.w = (v0.w - mean) * rs * ga.w + ba.w;
    o1.x = (v1.x - mean) * rs * gb.x + bb.x;
    o1.y = (v1.y - mean) * rs * gb.y + bb.y;
    o1.z = (v1.z - mean) * rs * gb.z + bb.z;
    o1.w = (v1.w - mean) * rs * gb.w + bb.w;
    *(float4*)(y + c0) = o0;
    *(float4*)(y + 128 + c0) = o1;
}

// ---------------------------------------------------------------------------
// tf32 tensor-core GEMM, double-buffered cp.async staging.
// BM=128, BN=64, BK=16; 8 warps, warp tile 32x32.
// ---------------------------------------------------------------------------
template<bool BIAS, bool RES, bool GELU>
__global__ __launch_bounds__(256, 2) void gemm_mma(
    const float* __restrict__ A, const float* __restrict__ W,
    const float* __restrict__ bias, const float* __restrict__ Res,
    float* __restrict__ C, int M, int N, int K)
{
    __shared__ float As[2][128][36];
    __shared__ float Bs[2][16][72];
    const int n0 = blockIdx.x * 64;
    const int m0 = blockIdx.y * 128;
    const int tid  = threadIdx.x;
    const int w    = tid >> 5;
    const int lane = tid & 31;
    const int wm = (w & 3) * 32;
    const int wn = (w >> 2) * 32;
    const int gr = lane >> 2, q4 = lane & 3;

    float acc[2][4][4];
#pragma unroll
    for (int mi = 0; mi < 2; mi++)
#pragma unroll
        for (int ni = 0; ni < 4; ni++)
#pragma unroll
            for (int j = 0; j < 4; j++) acc[mi][ni][j] = 0.f;

    const int ar  = tid >> 2;
    const int ac4 = tid & 3;
    const int bk  = tid >> 4;
    const int bc4 = tid & 15;

    const int KT = K >> 4;

    auto stage = [&](int s, int k0) {
#pragma unroll
        for (int l = 0; l < 2; l++) {
            int row = ar + l * 64;
            if (m0 + row < M)
                cp16(&As[s][row][ac4 * 4], A + (size_t)(m0 + row) * K + k0 + ac4 * 4);
            else
                *(float4*)&As[s][row][ac4 * 4] = make_float4(0.f, 0.f, 0.f, 0.f);
        }
        cp16(&Bs[s][bk][bc4 * 4], W + (size_t)(k0 + bk) * N + n0 + bc4 * 4);
    };

    stage(0, 0);
    CP_COMMIT();

    for (int kt = 0; kt < KT; kt++) {
        if (kt + 1 < KT) stage((kt + 1) & 1, (kt + 1) * 16);
        CP_COMMIT();
        CP_WAIT1();
        __syncthreads();
        const int buf = kt & 1;
#pragma unroll
        for (int kk = 0; kk < 2; kk++) {
            unsigned a[2][4];
#pragma unroll
            for (int mi = 0; mi < 2; mi++) {
                int rb = wm + mi * 16;
                a[mi][0] = __float_as_uint(As[buf][rb + gr    ][kk * 8 + q4]);
                a[mi][1] = __float_as_uint(As[buf][rb + gr + 8][kk * 8 + q4]);
                a[mi][2] = __float_as_uint(As[buf][rb + gr    ][kk * 8 + q4 + 4]);
                a[mi][3] = __float_as_uint(As[buf][rb + gr + 8][kk * 8 + q4 + 4]);
            }
#pragma unroll
            for (int ni = 0; ni < 4; ni++) {
                unsigned b0 = __float_as_uint(Bs[buf][kk * 8 + q4    ][wn + ni * 8 + gr]);
                unsigned b1 = __float_as_uint(Bs[buf][kk * 8 + q4 + 4][wn + ni * 8 + gr]);
#pragma unroll
                for (int mi = 0; mi < 2; mi++)
                    mma_tf32(acc[mi][ni], a[mi], b0, b1);
            }
        }
        __syncthreads();
    }

#pragma unroll
    for (int mi = 0; mi < 2; mi++) {
        int row0 = m0 + wm + mi * 16 + gr;
        int row1 = row0 + 8;
#pragma unroll
        for (int ni = 0; ni < 4; ni++) {
            int cn = n0 + wn + ni * 8 + 2 * q4;
            float b0v = 0.f, b1v = 0.f;
            if (BIAS) { b0v = bias[cn]; b1v = bias[cn + 1]; }
#pragma unroll
            for (int half = 0; half < 2; half++) {
                int r = half ? row1 : row0;
                if (r >= M) continue;
                float v0 = acc[mi][ni][half * 2 + 0] + b0v;
                float v1 = acc[mi][ni][half * 2 + 1] + b1v;
                if (GELU) {
                    v0 = 0.5f * v0 * (1.f + erff(v0 * 0.70710678118654752f));
                    v1 = 0.5f * v1 * (1.f + erff(v1 * 0.70710678118654752f));
                }
                if (RES) {
                    v0 += Res[(size_t)r * N + cn];
                    v1 += Res[(size_t)r * N + cn + 1];
                }
                *(float2*)(C + (size_t)r * N + cn) = make_float2(v0, v1);
            }
        }
    }
}

// ---------------------------------------------------------------------------
// Tensor-core attention v4: 512 threads / 16 warps, one 16-row m-fragment per
// warp, CTA = 256 q-rows of one (b,h). Double-buffered cp.async K/V.
// Mask stream now 100%-sector-coalesced: each lane LDG.128s 4 consecutive
// keys of one row (lanes l and l+16 jointly cover 32 contiguous bytes/row),
// redistributed to the C-fragment layout via 8 shuffles per step.
// ---------------------------------------------------------------------------
__global__ __launch_bounds__(512) void attn_mma_kernel(
    const float* __restrict__ Q, const float* __restrict__ KV,
    const float* __restrict__ MU, float* __restrict__ O)
{
    extern __shared__ float sm_att[];
    float (*Ks)[64][36] = reinterpret_cast<float (*)[64][36]>(sm_att);
    float (*Vs)[64][36] = reinterpret_cast<float (*)[64][36]>(sm_att + 2 * 64 * 36);

    const int m0 = blockIdx.x * 256;
    const int h  = blockIdx.y;
    const int b  = blockIdx.z;
    const int tid  = threadIdx.x;
    const int w    = tid >> 5;          // 0..15
    const int lane = tid & 31;
    const int gr   = lane >> 2;
    const int q4   = lane & 3;

    // Q fragment: rows m0 + w*16 + gr(+8), cols h*32 + kk*8 + q4(+4)
    unsigned qa[4][4];
    {
        const float* qb = Q + ((size_t)(b * NT + m0 + w * 16)) * 256 + h * HD;
#pragma unroll
        for (int kk = 0; kk < 4; kk++) {
            qa[kk][0] = __float_as_uint(qb[(size_t)gr * 256 + kk * 8 + q4]);
            qa[kk][1] = __float_as_uint(qb[(size_t)(gr + 8) * 256 + kk * 8 + q4]);
            qa[kk][2] = __float_as_uint(qb[(size_t)gr * 256 + kk * 8 + q4 + 4]);
            qa[kk][3] = __float_as_uint(qb[(size_t)(gr + 8) * 256 + kk * 8 + q4 + 4]);
        }
    }

    const float* kb = KV + (size_t)b * NK * 512 + h * HD;
    const float* vb = kb + 256;

    const int lr = tid >> 3;    // 0..63 : one float4 per thread per tile
    const int lc = tid & 7;

    auto stageK = [&](int s, int cb) {
        int nv = NK - cb;
        if (lr < nv) cp16(&Ks[s][lr][lc * 4], kb + (size_t)(cb + lr) * 512 + lc * 4);
        else         *(float4*)&Ks[s][lr][lc * 4] = make_float4(0.f, 0.f, 0.f, 0.f);
    };
    auto stageV = [&](int s, int cb) {
        int nv = NK - cb;
        if (lr < nv) cp16(&Vs[s][lr][lc * 4], vb + (size_t)(cb + lr) * 512 + lc * 4);
        else         *(float4*)&Vs[s][lr][lc * 4] = make_float4(0.f, 0.f, 0.f, 0.f);
    };

    // ---- pass A: per-segment exp sums. z[rowhalf][seg] ----
    float z[2][2] = {{0.f, 0.f}, {0.f, 0.f}};

    stageK(0, 0);
    CP_COMMIT();
    for (int t = 0; t < 37; t++) {
        const int cb = t * 64;
        if (t + 1 < 37) stageK((t + 1) & 1, cb + 64);
        CP_COMMIT();
        CP_WAIT1();
        __syncthreads();
        const float (*K_)[36] = Ks[t & 1];
#pragma unroll
        for (int nn = 0; nn < 8; nn++) {
            float c[4] = {0.f, 0.f, 0.f, 0.f};
#pragma unroll
            for (int kk = 0; kk < 4; kk++) {
                unsigned b0 = __float_as_uint(K_[nn * 8 + gr][kk * 8 + q4]);
                unsigned b1 = __float_as_uint(K_[nn * 8 + gr][kk * 8 + q4 + 4]);
                mma_tf32(c, qa[kk], b0, b1);
            }
            const int g0 = cb + nn * 8 + 2 * q4;   // even; g0,g0+1 same seg/bounds
            if (g0 < NK) {
                int sg = (g0 < CLSN) ? 0 : 1;
                z[0][sg] += __expf(c[0] * ATT_SCALE) + __expf(c[1] * ATT_SCALE);
                z[1][sg] += __expf(c[2] * ATT_SCALE) + __expf(c[3] * ATT_SCALE);
            }
        }
        __syncthreads();
    }
    float iz[2][2];
#pragma unroll
    for (int rh = 0; rh < 2; rh++)
#pragma unroll
        for (int sg = 0; sg < 2; sg++) {
            float v = z[rh][sg];
            v += __shfl_xor_sync(~0u, v, 1);
            v += __shfl_xor_sync(~0u, v, 2);
            iz[rh][sg] = 1.f / v;
        }

    // ---- pass B ----
    float av[4][4];
#pragma unroll
    for (int i = 0; i < 4; i++)
#pragma unroll
        for (int j = 0; j < 4; j++) av[i][j] = 0.f;
    float ws0 = 0.f, ws1 = 0.f;

    // Coalesced mask staging: lane (rl = lane&15, kloff = (lane>>4)*4) loads
    // the float4 of row (w*16+rl), keys step*8+kloff .. +3. Lanes l, l+16
    // together cover 32 contiguous bytes of each row -> 100% sector use.
    const int rl    = lane & 15;
    const int kloff = (lane >> 4) * 4;
    const float* mwarp = MU + (((size_t)(b * HDS + h)) * NK + CLSN + m0 + w * 16 + rl) * NK;
    float4 pm[4];
    auto ldm = [&](int s, int d) {
        int off = s * 8 + kloff;
        if (off + 4 <= NK) pm[d] = *(const float4*)(mwarp + off);
        else               pm[d] = make_float4(0.f, 0.f, 0.f, 0.f);
    };
    ldm(0, 0); ldm(1, 1); ldm(2, 2); ldm(3, 3);

    // shuffle sources: value (row r, key 2q4) lives in lane r + 16*(q4>>1),
    // comps (x,y) if q4 even else (z,w).
    const int srcA = gr + ((q4 >> 1) << 4);        // row gr
    const int srcB = gr + 8 + ((q4 >> 1) << 4);    // row gr+8
    const int base = lane & ~3;
    const int s0l = base + (q4 >> 1);
    const int s1l = s0l + 2;

    stageK(0, 0);
    stageV(0, 0);
    CP_COMMIT();
    for (int t = 0; t < 37; t++) {
        const int cb = t * 64;
        if (t + 1 < 37) { stageK((t + 1) & 1, cb + 64); stageV((t + 1) & 1, cb + 64); }
        CP_COMMIT();
        CP_WAIT1();
        __syncthreads();
        const float (*K_)[36] = Ks[t & 1];
        const float (*V_)[36] = Vs[t & 1];
#pragma unroll
        for (int nn = 0; nn < 8; nn++) {
            const int step = t * 8 + nn;           // step&3 == nn&3 (t*8 % 4 == 0)
            const int d = nn & 3;
            float c[4] = {0.f, 0.f, 0.f, 0.f};
#pragma unroll
            for (int kk = 0; kk < 4; kk++) {
                unsigned b0 = __float_as_uint(K_[nn * 8 + gr][kk * 8 + q4]);
                unsigned b1 = __float_as_uint(K_[nn * 8 + gr][kk * 8 + q4 + 4]);
                mma_tf32(c, qa[kk], b0, b1);
            }
            // redistribute mask to C-layout (8 shuffles)
            float ax = __shfl_sync(~0u, pm[d].x, srcA);
            float ay = __shfl_sync(~0u, pm[d].y, srcA);
            float az = __shfl_sync(~0u, pm[d].z, srcA);
            float aw = __shfl_sync(~0u, pm[d].w, srcA);
            float bx = __shfl_sync(~0u, pm[d].x, srcB);
            float by = __shfl_sync(~0u, pm[d].y, srcB);
            float bz = __shfl_sync(~0u, pm[d].z, srcB);
            float bw = __shfl_sync(~0u, pm[d].w, srcB);
            const bool odd = (q4 & 1);
            float mA0 = odd ? az : ax, mA1 = odd ? aw : ay;
            float mB0 = odd ? bz : bx, mB1 = odd ? bw : by;
            ldm(step + 4, d);                      // prefetch 4 steps ahead

            const int g0 = cb + nn * 8 + 2 * q4;
            float wv0 = 0.f, wv1 = 0.f, wv2 = 0.f, wv3 = 0.f;
            if (g0 < NK) {
                const int sg = (g0 < CLSN) ? 0 : 1;
                if (mA0 >= 0.3f) wv0 = exp01(__expf(c[0] * ATT_SCALE) * iz[0][sg]);
                if (mA1 >= 0.3f) wv1 = exp01(__expf(c[1] * ATT_SCALE) * iz[0][sg]);
                if (mB0 >= 0.3f) wv2 = exp01(__expf(c[2] * ATT_SCALE) * iz[1][sg]);
                if (mB1 >= 0.3f) wv3 = exp01(__expf(c[3] * ATT_SCALE) * iz[1][sg]);
            }
            ws0 += wv0 + wv1;
            ws1 += wv2 + wv3;
            // C->A fragment conversion (within quad)
            float u0 = __shfl_sync(~0u, wv0, s0l);
            float u1 = __shfl_sync(~0u, wv1, s0l);
            float u2 = __shfl_sync(~0u, wv2, s0l);
            float u3 = __shfl_sync(~0u, wv3, s0l);
            float v0 = __shfl_sync(~0u, wv0, s1l);
            float v1 = __shfl_sync(~0u, wv1, s1l);
            float v2 = __shfl_sync(~0u, wv2, s1l);
            float v3 = __shfl_sync(~0u, wv3, s1l);
            unsigned wa[4];
            wa[0] = __float_as_uint((q4 & 1) ? u1 : u0);
            wa[1] = __float_as_uint((q4 & 1) ? u3 : u2);
            wa[2] = __float_as_uint((q4 & 1) ? v1 : v0);
            wa[3] = __float_as_uint((q4 & 1) ? v3 : v2);
#pragma unroll
            for (int nn2 = 0; nn2 < 4; nn2++) {
                unsigned b0 = __float_as_uint(V_[nn * 8 + q4    ][nn2 * 8 + gr]);
                unsigned b1 = __float_as_uint(V_[nn * 8 + q4 + 4][nn2 * 8 + gr]);
                mma_tf32(av[nn2], wa, b0, b1);
            }
        }
        __syncthreads();
    }
#pragma unroll
    for (int o = 1; o <= 2; o <<= 1) {
        ws0 += __shfl_xor_sync(~0u, ws0, o);
        ws1 += __shfl_xor_sync(~0u, ws1, o);
    }
    const float inv0 = 1.f / ws0;
    const float inv1 = 1.f / ws1;

    float* ob0 = O + ((size_t)(b * NT + m0 + w * 16 + gr)) * 256 + h * HD;
    float* ob1 = ob0 + (size_t)8 * 256;
#pragma unroll
    for (int nn2 = 0; nn2 < 4; nn2++) {
        *(float2*)(ob0 + nn2 * 8 + 2 * q4) = make_float2(av[nn2][0] * inv0, av[nn2][1] * inv0);
        *(float2*)(ob1 + nn2 * 8 + 2 * q4) = make_float2(av[nn2][2] * inv1, av[nn2][3] * inv1);
    }
}

// ---------------------------------------------------------------------------
// (B, T, C) -> (B, C, H, W) transpose
// ---------------------------------------------------------------------------
__global__ __launch_bounds__(256) void transpose_k(
    const float* __restrict__ Y, float* __restrict__ O)
{
    __shared__ float t[32][33];
    const int b = blockIdx.z;
    const int t0 = blockIdx.x * 32;
    const int c0 = blockIdx.y * 32;
    for (int i = threadIdx.y; i < 32; i += 8)
        t[i][threadIdx.x] = Y[((size_t)(b * NT + t0 + i)) * 256 + c0 + threadIdx.x];
    __syncthreads();
    for (int i = threadIdx.y; i < 32; i += 8)
        O[((size_t)(b * 256 + c0 + i)) * NT + t0 + threadIdx.x] = t[threadIdx.x][i];
}

// ---------------------------------------------------------------------------
extern "C" void kernel_launch(void* const* d_in, const int* in_sizes, int n_in,
                              void* d_out, int out_size)
{
    const float* x_query = (const float*)d_in[0];
    const float* x_key   = (const float*)d_in[1];
    const float* mask_u  = (const float*)d_in[2];
    const float* g1  = (const float*)d_in[3];
    const float* be1 = (const float*)d_in[4];
    const float* g2  = (const float*)d_in[5];
    const float* be2 = (const float*)d_in[6];
    const float* g3  = (const float*)d_in[7];
    const float* be3 = (const float*)d_in[8];
    const float* Wq  = (const float*)d_in[9];
    const float* Wkv = (const float*)d_in[10];
    // d_in[11] = Wcls: dead code (outputs sliced away by x[:, CLS:])
    const float* Wp  = (const float*)d_in[12];
    const float* bp  = (const float*)d_in[13];
    const float* W1  = (const float*)d_in[14];
    const float* bf1 = (const float*)d_in[15];
    const float* W2  = (const float*)d_in[16];
    const float* bf2 = (const float*)d_in[17];
    float* out = (float*)d_out;

    static float *xq = nullptr, *qin, *kin, *q, *kv, *ao, *x2, *ln3, *hbuf, *y;
    if (!xq) {
        cudaGetSymbolAddress((void**)&xq,   g_xq);
        cudaGetSymbolAddress((void**)&qin,  g_qin);
        cudaGetSymbolAddress((void**)&kin,  g_kin);
        cudaGetSymbolAddress((void**)&q,    g_q);
        cudaGetSymbolAddress((void**)&kv,   g_kv);
        cudaGetSymbolAddress((void**)&ao,   g_ao);
        cudaGetSymbolAddress((void**)&x2,   g_x2);
        cudaGetSymbolAddress((void**)&ln3,  g_ln3);
        cudaGetSymbolAddress((void**)&hbuf, g_h);
        cudaGetSymbolAddress((void**)&y,    g_y);
        cudaFuncSetAttribute(attn_mma_kernel,
                             cudaFuncAttributeMaxDynamicSharedMemorySize, ATT_SMEM);
    }

    // 1. LN(x_query) with NCHW gather; writes xq (residual) + qin
    ln_q_kernel<<<dim3(NT / 32, BB), 256>>>(x_query, g1, be1, xq, qin);
    // 2. LN(x_key) -> kin
    ln_row_kernel<<<(KTOT + 7) / 8, 256>>>(x_key, g2, be2, kin, KTOT);
    // 3. Q = qin @ Wq
    gemm_mma<false, false, false><<<dim3(4, (MTOT + 127) / 128), 256>>>(
        qin, Wq, nullptr, nullptr, q, MTOT, 256, 256);
    // 4. KV = kin @ Wkv
    gemm_mma<false, false, false><<<dim3(8, (KTOT + 127) / 128), 256>>>(
        kin, Wkv, nullptr, nullptr, kv, KTOT, 512, 256);
    // 5. attention (tf32 mma, coalesced mask) -> ao
    attn_mma_kernel<<<dim3(NT / 256, HDS, BB), 512, ATT_SMEM>>>(q, kv, mask_u, ao);
    // 6. x2 = xq + (ao @ Wp + bp)
    gemm_mma<true, true, false><<<dim3(4, (MTOT + 127) / 128), 256>>>(
        ao, Wp, bp, xq, x2, MTOT, 256, 256);
    // 7. ln3 = LN(x2)
    ln_row_kernel<<<(MTOT + 7) / 8, 256>>>(x2, g3, be3, ln3, MTOT);
    // 8. h = gelu(ln3 @ W1 + bf1)
    gemm_mma<true, false, true><<<dim3(16, (MTOT + 127) / 128), 256>>>(
        ln3, W1, bf1, nullptr, hbuf, MTOT, 1024, 256);
    // 9. y = x2 + (h @ W2 + bf2)
    gemm_mma<true, true, false><<<dim3(4, (MTOT + 127) / 128), 256>>>(
        hbuf, W2, bf2, x2, y, MTOT, 256, 1024);
    // 10. transpose to (B, C, H, W)
    transpose_k<<<dim3(NT / 32, 256 / 32, BB), dim3(32, 8)>>>(y, out);
}